// round 4
// baseline (speedup 1.0000x reference)
#include <cuda_runtime.h>
#include <math.h>

// ---------------- problem constants ----------------
constexpr int kB   = 16384;
constexpr int kIN  = 1024;
constexpr int kE   = 6;
constexpr int kEH1 = 256;
constexpr int kEH2 = 128;
constexpr int kEO  = 10;
constexpr int kGH  = 64;

// ---------------- scratch (device globals: no allocs allowed) ----------------
__device__ float g_H1[(size_t)kE * kB * kEH1];   // relu(x @ Ew1 + b1)  [E,B,256]
__device__ float g_H2[(size_t)kE * kB * kEH2];   // relu(H1 @ Ew2 + b2) [E,B,128]
__device__ float g_EO[(size_t)kE * kB * kEO];    // H2 @ Ew3 + b3       [E,B,10]

// =====================================================================
// Generic tiled SGEMM with bias + optional ReLU.
//   C[z][M,N] = act(A[z][M,K] @ W[z][K,N] + bias[z][N])
// BM=128, BN=64, BK=32, 256 threads, 8x4 microtile.
// =====================================================================
__global__ __launch_bounds__(256)
void sgemm_bias_relu(const float* __restrict__ A, const float* __restrict__ W,
                     const float* __restrict__ bias, float* __restrict__ C,
                     int N, int K,
                     size_t aStride, size_t wStride, size_t bStride, size_t cStride,
                     int doRelu)
{
    constexpr int BM = 128, BN = 64, BK = 32;
    __shared__ float As[BK][BM + 4];   // As[k][m], +4 pad keeps float4 reads aligned, reduces store conflicts
    __shared__ float Bs[BK][BN];       // Bs[k][n]

    const float* Ae = A    + (size_t)blockIdx.z * aStride;
    const float* We = W    + (size_t)blockIdx.z * wStride;
    const float* be = bias + (size_t)blockIdx.z * bStride;
    float*       Ce = C    + (size_t)blockIdx.z * cStride;

    const int tid = threadIdx.x;
    const int tx  = tid & 15;     // 0..15 -> 4 cols each
    const int ty  = tid >> 4;     // 0..15 -> 8 rows each
    const int rowBase = blockIdx.y * BM;
    const int colBase = blockIdx.x * BN;

    const int aRow = tid >> 3;          // 0..31
    const int aK   = (tid & 7) * 4;     // 0,4,...,28

    float acc[8][4];
#pragma unroll
    for (int i = 0; i < 8; ++i)
#pragma unroll
        for (int j = 0; j < 4; ++j) acc[i][j] = 0.f;

    for (int t = 0; t < K; t += BK) {
        // --- load A tile (128 x 32), store transposed ---
#pragma unroll
        for (int i = 0; i < 4; ++i) {
            int m = aRow + i * 32;
            float4 v = *(const float4*)(Ae + (size_t)(rowBase + m) * K + t + aK);
            As[aK + 0][m] = v.x;
            As[aK + 1][m] = v.y;
            As[aK + 2][m] = v.z;
            As[aK + 3][m] = v.w;
        }
        // --- load W tile (32 x 64) ---
#pragma unroll
        for (int i = 0; i < 2; ++i) {
            int idx = tid + i * 256;
            int kr  = idx >> 4;
            int c4  = (idx & 15) * 4;
            *(float4*)&Bs[kr][c4] = *(const float4*)(We + (size_t)(t + kr) * N + colBase + c4);
        }
        __syncthreads();

#pragma unroll
        for (int kk = 0; kk < BK; ++kk) {
            float4 a0 = *(const float4*)&As[kk][ty * 8];
            float4 a1 = *(const float4*)&As[kk][ty * 8 + 4];
            float4 b0 = *(const float4*)&Bs[kk][tx * 4];
            float av[8] = {a0.x, a0.y, a0.z, a0.w, a1.x, a1.y, a1.z, a1.w};
            float bv[4] = {b0.x, b0.y, b0.z, b0.w};
#pragma unroll
            for (int i = 0; i < 8; ++i)
#pragma unroll
                for (int j = 0; j < 4; ++j)
                    acc[i][j] = fmaf(av[i], bv[j], acc[i][j]);
        }
        __syncthreads();
    }

    // --- epilogue: bias (+relu), vectorized store ---
    float4 bb = *(const float4*)(be + colBase + tx * 4);
    float bvv[4] = {bb.x, bb.y, bb.z, bb.w};
#pragma unroll
    for (int i = 0; i < 8; ++i) {
        int m = rowBase + ty * 8 + i;
        float4 o;
        o.x = acc[i][0] + bvv[0];
        o.y = acc[i][1] + bvv[1];
        o.z = acc[i][2] + bvv[2];
        o.w = acc[i][3] + bvv[3];
        if (doRelu) {
            o.x = fmaxf(o.x, 0.f); o.y = fmaxf(o.y, 0.f);
            o.z = fmaxf(o.z, 0.f); o.w = fmaxf(o.w, 0.f);
        }
        *(float4*)(Ce + (size_t)m * N + colBase + tx * 4) = o;
    }
}

// =====================================================================
// Expert layer 3: eo[e,b,:] = H2[e,b,:] @ Ew3[e] + Eb3[e]   (K=128, N=10)
// One warp per (e,b) row; Ew3[e] cached in shared.
// =====================================================================
__global__ __launch_bounds__(256)
void expert_l3_kernel(const float* __restrict__ Ew3, const float* __restrict__ Eb3)
{
    const int e = blockIdx.y;
    __shared__ float Ws[kEH2 * kEO];   // 1280 floats
    __shared__ float bs[kEO];
    for (int i = threadIdx.x; i < kEH2 * kEO; i += 256)
        Ws[i] = Ew3[(size_t)e * kEH2 * kEO + i];
    if (threadIdx.x < kEO) bs[threadIdx.x] = Eb3[e * kEO + threadIdx.x];
    __syncthreads();

    const int warp = threadIdx.x >> 5;
    const int lane = threadIdx.x & 31;
    const int b    = blockIdx.x * 8 + warp;

    const float* h = g_H2 + ((size_t)e * kB + b) * kEH2;
    float4 hv = *(const float4*)(h + lane * 4);

    float o[kEO];
#pragma unroll
    for (int j = 0; j < kEO; ++j) {
        o[j] = hv.x * Ws[(lane * 4 + 0) * kEO + j]
             + hv.y * Ws[(lane * 4 + 1) * kEO + j]
             + hv.z * Ws[(lane * 4 + 2) * kEO + j]
             + hv.w * Ws[(lane * 4 + 3) * kEO + j];
    }
#pragma unroll
    for (int j = 0; j < kEO; ++j)
#pragma unroll
        for (int off = 16; off; off >>= 1)
            o[j] += __shfl_xor_sync(0xffffffffu, o[j], off);

#pragma unroll
    for (int j = 0; j < kEO; ++j)
        if (lane == j)
            g_EO[((size_t)e * kB + b) * kEO + j] = o[j] + bs[j];
}

// =====================================================================
// Fused per-sample kernel (ONLY the selected domain — 20x less gate/tower
// work than the reference): gate MLP + softmax + MMoE combine + avg expert
// + tower MLP + sigmoid + all three outputs.
// One warp per sample.
// =====================================================================
__global__ __launch_bounds__(256)
void fused_gate_tower(const float* __restrict__ x, const int* __restrict__ dom,
                      const float* __restrict__ Gw1, const float* __restrict__ Gb1,
                      const float* __restrict__ Gw2, const float* __restrict__ Gb2,
                      const float* __restrict__ Tw1, const float* __restrict__ Tb1,
                      const float* __restrict__ Tw2, const float* __restrict__ Tb2,
                      float* __restrict__ out)
{
    const int warp = threadIdx.x >> 5;
    const int lane = threadIdx.x & 31;
    const int b    = blockIdx.x * 8 + warp;
    const int d    = dom[b];

    // ---- gate hidden: g[64] = relu(x[b] @ Gw1[d] + Gb1[d]) ----
    const float* xr = x + (size_t)b * kIN;
    const float* W1 = Gw1 + (size_t)d * kIN * kGH;
    float acc0 = 0.f, acc1 = 0.f;
    for (int k0 = 0; k0 < kIN; k0 += 32) {
        float xv = xr[k0 + lane];
#pragma unroll
        for (int kk = 0; kk < 32; ++kk) {
            float xs = __shfl_sync(0xffffffffu, xv, kk);
            const float* wrow = W1 + (size_t)(k0 + kk) * kGH;
            acc0 = fmaf(xs, wrow[lane],      acc0);
            acc1 = fmaf(xs, wrow[lane + 32], acc1);
        }
    }
    float g0 = fmaxf(acc0 + Gb1[d * kGH + lane],      0.f);
    float g1 = fmaxf(acc1 + Gb1[d * kGH + lane + 32], 0.f);

    // ---- gate logits[6] = g @ Gw2[d] + Gb2[d], softmax ----
    float logit[kE];
#pragma unroll
    for (int e = 0; e < kE; ++e)
        logit[e] = g0 * Gw2[((size_t)d * kGH + lane) * kE + e]
                 + g1 * Gw2[((size_t)d * kGH + lane + 32) * kE + e];
#pragma unroll
    for (int e = 0; e < kE; ++e)
#pragma unroll
        for (int off = 16; off; off >>= 1)
            logit[e] += __shfl_xor_sync(0xffffffffu, logit[e], off);

    float mx = -1e30f;
#pragma unroll
    for (int e = 0; e < kE; ++e) {
        logit[e] += Gb2[d * kE + e];
        mx = fmaxf(mx, logit[e]);
    }
    float se = 0.f;
    float gw[kE];
#pragma unroll
    for (int e = 0; e < kE; ++e) { gw[e] = expf(logit[e] - mx); se += gw[e]; }
    float inv = 1.f / se;

    // ---- eo gather: avg over experts + MMoE combine for domain d ----
    float mmoe = 0.f;
    if (lane < kEO) {
        float avg = 0.f;
#pragma unroll
        for (int e = 0; e < kE; ++e) {
            float v = g_EO[((size_t)e * kB + b) * kEO + lane];
            avg  += v;
            mmoe  = fmaf(gw[e] * inv, v, mmoe);
        }
        out[kB + (size_t)b * kEO + lane]            = avg * (1.f / 6.f);  // avg_expert_repr
        out[kB + (size_t)kB * kEO + (size_t)b * kEO + lane] = mmoe;       // selected_mmoe
    }

    // ---- broadcast mmoe[10] to all lanes ----
    float mm[kEO];
#pragma unroll
    for (int o = 0; o < kEO; ++o)
        mm[o] = __shfl_sync(0xffffffffu, mmoe, o);

    // ---- tower: th[64] = relu(mmoe @ Tw1[d] + Tb1[d]); out = sigmoid(th @ Tw2[d] + Tb2[d]) ----
    float th0 = Tb1[d * 64 + lane];
    float th1 = Tb1[d * 64 + lane + 32];
#pragma unroll
    for (int o = 0; o < kEO; ++o) {
        th0 = fmaf(mm[o], Tw1[((size_t)d * kEO + o) * 64 + lane],      th0);
        th1 = fmaf(mm[o], Tw1[((size_t)d * kEO + o) * 64 + lane + 32], th1);
    }
    th0 = fmaxf(th0, 0.f);
    th1 = fmaxf(th1, 0.f);

    float s = th0 * Tw2[d * 64 + lane] + th1 * Tw2[d * 64 + lane + 32];
#pragma unroll
    for (int off = 16; off; off >>= 1)
        s += __shfl_xor_sync(0xffffffffu, s, off);

    if (lane == 0) {
        float z = s + Tb2[d];
        out[b] = 1.f / (1.f + expf(-z));   // selected_outputs
    }
}

// =====================================================================
// launch
// =====================================================================
extern "C" void kernel_launch(void* const* d_in, const int* in_sizes, int n_in,
                              void* d_out, int out_size)
{
    const float* x   = (const float*)d_in[0];
    const int*   dom = (const int*)  d_in[1];
    const float* Ew1 = (const float*)d_in[2];
    const float* Eb1 = (const float*)d_in[3];
    const float* Ew2 = (const float*)d_in[4];
    const float* Eb2 = (const float*)d_in[5];
    const float* Ew3 = (const float*)d_in[6];
    const float* Eb3 = (const float*)d_in[7];
    const float* Gw1 = (const float*)d_in[8];
    const float* Gb1 = (const float*)d_in[9];
    const float* Gw2 = (const float*)d_in[10];
    const float* Gb2 = (const float*)d_in[11];
    const float* Tw1 = (const float*)d_in[12];
    const float* Tb1 = (const float*)d_in[13];
    const float* Tw2 = (const float*)d_in[14];
    const float* Tb2 = (const float*)d_in[15];
    float* out = (float*)d_out;

    float *H1, *H2;
    cudaGetSymbolAddress((void**)&H1, g_H1);
    cudaGetSymbolAddress((void**)&H2, g_H2);

    // Expert L1: [16384,1024] @ [1024,256] per expert, relu
    sgemm_bias_relu<<<dim3(kEH1 / 64, kB / 128, kE), 256>>>(
        x, Ew1, Eb1, H1,
        kEH1, kIN,
        /*aStride=*/0,
        /*wStride=*/(size_t)kIN * kEH1,
        /*bStride=*/kEH1,
        /*cStride=*/(size_t)kB * kEH1,
        /*relu=*/1);

    // Expert L2: [16384,256] @ [256,128] per expert, relu
    sgemm_bias_relu<<<dim3(kEH2 / 64, kB / 128, kE), 256>>>(
        H1, Ew2, Eb2, H2,
        kEH2, kEH1,
        /*aStride=*/(size_t)kB * kEH1,
        /*wStride=*/(size_t)kEH1 * kEH2,
        /*bStride=*/kEH2,
        /*cStride=*/(size_t)kB * kEH2,
        /*relu=*/1);

    // Expert L3: [16384,128] @ [128,10] per expert (no activation)
    expert_l3_kernel<<<dim3(kB / 8, kE), 256>>>(Ew3, Eb3);

    // Selected-domain gate + MMoE + tower + outputs
    fused_gate_tower<<<kB / 8, 256>>>(x, dom, Gw1, Gb1, Gw2, Gb2,
                                      Tw1, Tb1, Tw2, Tb2, out);
}

// round 9
// speedup vs baseline: 1.7862x; 1.7862x over previous
#include <cuda_runtime.h>
#include <cuda_bf16.h>
#include <math.h>
#include <stdint.h>

// ---------------- problem constants ----------------
constexpr int kB   = 16384;
constexpr int kIN  = 1024;
constexpr int kE   = 6;
constexpr int kEH1 = 256;
constexpr int kEH2 = 128;
constexpr int kEO  = 10;
constexpr int kGH  = 64;

// ---------------- scratch (device globals: no allocs allowed) ----------------
__device__ __nv_bfloat16 g_Xhi[(size_t)kB * kIN];
__device__ __nv_bfloat16 g_Xlo[(size_t)kB * kIN];
__device__ __nv_bfloat16 g_W1hi[(size_t)kE * kEH1 * kIN];   // [E][N=256][K=1024] (transposed)
__device__ __nv_bfloat16 g_W1lo[(size_t)kE * kEH1 * kIN];
__device__ __nv_bfloat16 g_W2hi[(size_t)kE * kEH2 * kEH1];  // [E][N=128][K=256]
__device__ __nv_bfloat16 g_W2lo[(size_t)kE * kEH2 * kEH1];
__device__ __nv_bfloat16 g_H1hi[(size_t)kE * kB * kEH1];    // relu(L1) split
__device__ __nv_bfloat16 g_H1lo[(size_t)kE * kB * kEH1];
__device__ float g_H2[(size_t)kE * kB * kEH2];              // relu(L2) fp32
__device__ float g_EO[(size_t)kE * kB * kEO];               // L3 out

// =====================================================================
// PTX helpers (sm_80-era ISA only — the harness targets plain sm_103,
// so tcgen05 is unavailable; HMMA via mma.sync is the tensor path).
// =====================================================================
__device__ __forceinline__ uint32_t smem_u32(const void* p) {
    return (uint32_t)__cvta_generic_to_shared(p);
}
__device__ __forceinline__ void cp_async16(uint32_t dst, const void* src) {
    asm volatile("cp.async.cg.shared.global [%0], [%1], 16;" :: "r"(dst), "l"(src));
}
__device__ __forceinline__ void cp_commit() { asm volatile("cp.async.commit_group;" ::: "memory"); }
__device__ __forceinline__ void cp_wait1()  { asm volatile("cp.async.wait_group 1;" ::: "memory"); }

__device__ __forceinline__ void ldsm4(uint32_t& r0, uint32_t& r1, uint32_t& r2, uint32_t& r3,
                                      uint32_t addr) {
    asm volatile("ldmatrix.sync.aligned.m8n8.x4.shared.b16 {%0,%1,%2,%3}, [%4];"
                 : "=r"(r0), "=r"(r1), "=r"(r2), "=r"(r3) : "r"(addr));
}
__device__ __forceinline__ void mma16816(float* c, const uint32_t* a, uint32_t b0, uint32_t b1) {
    asm volatile("mma.sync.aligned.m16n8k16.row.col.f32.bf16.bf16.f32 "
                 "{%0,%1,%2,%3},{%4,%5,%6,%7},{%8,%9},{%0,%1,%2,%3};"
                 : "+f"(c[0]), "+f"(c[1]), "+f"(c[2]), "+f"(c[3])
                 : "r"(a[0]), "r"(a[1]), "r"(a[2]), "r"(a[3]), "r"(b0), "r"(b1));
}

// =====================================================================
// Prep: split x into bf16 hi/lo
// =====================================================================
__global__ __launch_bounds__(256)
void split_x_kernel(const float4* __restrict__ x,
                    __nv_bfloat162* __restrict__ hi, __nv_bfloat162* __restrict__ lo)
{
    size_t i = (size_t)blockIdx.x * 256 + threadIdx.x;
    float4 v = x[i];
    __nv_bfloat16 hx = __float2bfloat16(v.x), hy = __float2bfloat16(v.y);
    __nv_bfloat16 hz = __float2bfloat16(v.z), hw = __float2bfloat16(v.w);
    __nv_bfloat162 H0; H0.x = hx; H0.y = hy;
    __nv_bfloat162 H1; H1.x = hz; H1.y = hw;
    __nv_bfloat162 L0, L1;
    L0.x = __float2bfloat16(v.x - __bfloat162float(hx));
    L0.y = __float2bfloat16(v.y - __bfloat162float(hy));
    L1.x = __float2bfloat16(v.z - __bfloat162float(hz));
    L1.y = __float2bfloat16(v.w - __bfloat162float(hw));
    hi[2 * i] = H0; hi[2 * i + 1] = H1;
    lo[2 * i] = L0; lo[2 * i + 1] = L1;
}

// =====================================================================
// Prep: W [E][K][N] fp32 -> Wt hi/lo bf16 [E][N][K]
// =====================================================================
__global__ __launch_bounds__(256)
void transpose_split_kernel(const float* __restrict__ W,
                            __nv_bfloat16* __restrict__ hi, __nv_bfloat16* __restrict__ lo,
                            int K, int N)
{
    __shared__ float t[32][33];
    const int e = blockIdx.z;
    const float* We = W + (size_t)e * K * N;
    const int k0 = blockIdx.x * 32, n0 = blockIdx.y * 32;
    const int tx = threadIdx.x, ty = threadIdx.y;
    for (int i = ty; i < 32; i += 8)
        t[i][tx] = We[(size_t)(k0 + i) * N + n0 + tx];
    __syncthreads();
    for (int i = ty; i < 32; i += 8) {
        float v = t[tx][i];  // = W[k0+tx][n0+i]
        size_t o = ((size_t)e * N + n0 + i) * K + k0 + tx;
        __nv_bfloat16 h = __float2bfloat16(v);
        hi[o] = h;
        lo[o] = __float2bfloat16(v - __bfloat162float(h));
    }
}

// =====================================================================
// mma.sync split-bf16 GEMM:
//   C[e][M=16384, NTOT] = relu( A[e][M,KTOT] @ Bt[e][NTOT,KTOT]^T + bias[e][NTOT] )
// D += Ahi*Bhi + Alo*Bhi + Ahi*Blo  (fp32 accumulate in registers)
// CTA tile 128x64, BK=32, 2-stage cp.async pipeline.
// 8 warps (4m x 2n), warp tile 32x32, m16n8k16 HMMA, ldmatrix.x4 operands.
// Smem rows padded to 80B -> conflict-free ldmatrix.
// SPLIT_OUT: emit bf16 hi/lo pair (feeds next layer); else fp32.
// =====================================================================
template<int NTOT, int KTOT, bool SPLIT_OUT>
__global__ __launch_bounds__(256, 2)
void mma_gemm(const __nv_bfloat16* __restrict__ Ahb, const __nv_bfloat16* __restrict__ Alb,
              const __nv_bfloat16* __restrict__ Bh_all, const __nv_bfloat16* __restrict__ Bl_all,
              const float* __restrict__ bias, size_t aStride,
              float* __restrict__ Cf, __nv_bfloat16* __restrict__ Chi,
              __nv_bfloat16* __restrict__ Clo)
{
    constexpr int BK = 32;
    constexpr int NCHUNK = KTOT / BK;
    constexpr int ROWB = 80;                 // 64B of data + 16B pad per smem row
    constexpr int A_SZ = 128 * ROWB;         // 10240
    constexpr int B_SZ = 64 * ROWB;          // 5120
    constexpr int STAGE = 2 * A_SZ + 2 * B_SZ;  // 30720

    extern __shared__ char dsm[];
    const uint32_t sb = smem_u32(dsm);

    const int tid  = threadIdx.x;
    const int w    = tid >> 5;
    const int lane = tid & 31;
    const int e     = blockIdx.z;
    const int mBase = blockIdx.y * 128;
    const int nBase = blockIdx.x * 64;
    const int wm = (w & 3) * 32;
    const int wn = (w >> 2) * 32;

    const __nv_bfloat16* Ah = Ahb + (size_t)e * aStride;
    const __nv_bfloat16* Al = Alb + (size_t)e * aStride;
    const __nv_bfloat16* Bh = Bh_all + (size_t)e * NTOT * KTOT;
    const __nv_bfloat16* Bl = Bl_all + (size_t)e * NTOT * KTOT;

    auto load_chunk = [&](int c, int s) {
        const uint32_t st = sb + s * STAGE;
        // A: 128 rows x 4 granules x {hi,lo} = 1024; B: 64 x 4 x 2 = 512
#pragma unroll
        for (int g = tid; g < 1536; g += 256) {
            if (g < 1024) {
                int h   = g >> 9;
                int idx = g & 511;
                int row = idx >> 2, gr = idx & 3;
                const __nv_bfloat16* src =
                    (h ? Al : Ah) + (size_t)(mBase + row) * KTOT + c * BK + gr * 8;
                cp_async16(st + h * A_SZ + row * ROWB + gr * 16, src);
            } else {
                int gg  = g - 1024;
                int h   = gg >> 8;
                int idx = gg & 255;
                int row = idx >> 2, gr = idx & 3;
                const __nv_bfloat16* src =
                    (h ? Bl : Bh) + (size_t)(nBase + row) * KTOT + c * BK + gr * 8;
                cp_async16(st + 2 * A_SZ + h * B_SZ + row * ROWB + gr * 16, src);
            }
        }
    };

    float acc[2][4][4];
#pragma unroll
    for (int i = 0; i < 2; ++i)
#pragma unroll
        for (int j = 0; j < 4; ++j)
#pragma unroll
            for (int q = 0; q < 4; ++q) acc[i][j][q] = 0.f;

    load_chunk(0, 0); cp_commit();
    load_chunk(1, 1); cp_commit();

    const int lr = lane & 15;
    const int lc = (lane >> 4) * 16;   // byte offset of 8-col half

    for (int i = 0; i < NCHUNK; ++i) {
        const int s = i & 1;
        cp_wait1();
        __syncthreads();
        const uint32_t st     = sb + s * STAGE;
        const uint32_t aBaseH = st + wm * ROWB;
        const uint32_t aBaseL = aBaseH + A_SZ;
        const uint32_t bBaseH = st + 2 * A_SZ + wn * ROWB;
        const uint32_t bBaseL = bBaseH + B_SZ;

#pragma unroll
        for (int ks = 0; ks < 2; ++ks) {
            const uint32_t koff = ks * 32 + lc;
            uint32_t ah[2][4], bh[2][4];
            // hi fragments
#pragma unroll
            for (int mi = 0; mi < 2; ++mi)
                ldsm4(ah[mi][0], ah[mi][1], ah[mi][2], ah[mi][3],
                      aBaseH + (mi * 16 + lr) * ROWB + koff);
#pragma unroll
            for (int nj = 0; nj < 2; ++nj)
                ldsm4(bh[nj][0], bh[nj][1], bh[nj][2], bh[nj][3],
                      bBaseH + (nj * 16 + lr) * ROWB + koff);
            // term 1: Ahi * Bhi
#pragma unroll
            for (int mi = 0; mi < 2; ++mi)
#pragma unroll
                for (int nj = 0; nj < 2; ++nj)
#pragma unroll
                    for (int t = 0; t < 2; ++t)
                        mma16816(acc[mi][nj * 2 + t], ah[mi], bh[nj][t], bh[nj][t + 2]);
            // term 2: Alo * Bhi (then bh dies)
            {
                uint32_t al[2][4];
#pragma unroll
                for (int mi = 0; mi < 2; ++mi)
                    ldsm4(al[mi][0], al[mi][1], al[mi][2], al[mi][3],
                          aBaseL + (mi * 16 + lr) * ROWB + koff);
#pragma unroll
                for (int mi = 0; mi < 2; ++mi)
#pragma unroll
                    for (int nj = 0; nj < 2; ++nj)
#pragma unroll
                        for (int t = 0; t < 2; ++t)
                            mma16816(acc[mi][nj * 2 + t], al[mi], bh[nj][t], bh[nj][t + 2]);
            }
            // term 3: Ahi * Blo
            {
                uint32_t bl[2][4];
#pragma unroll
                for (int nj = 0; nj < 2; ++nj)
                    ldsm4(bl[nj][0], bl[nj][1], bl[nj][2], bl[nj][3],
                          bBaseL + (nj * 16 + lr) * ROWB + koff);
#pragma unroll
                for (int mi = 0; mi < 2; ++mi)
#pragma unroll
                    for (int nj = 0; nj < 2; ++nj)
#pragma unroll
                        for (int t = 0; t < 2; ++t)
                            mma16816(acc[mi][nj * 2 + t], ah[mi], bl[nj][t], bl[nj][t + 2]);
            }
        }
        __syncthreads();
        if (i + 2 < NCHUNK) load_chunk(i + 2, s);
        cp_commit();
    }

    // ---- epilogue: bias + relu, store ----
    const float* be = bias + e * NTOT;
    const int r0 = lane >> 2;
    const int c0 = (lane & 3) * 2;
#pragma unroll
    for (int mi = 0; mi < 2; ++mi) {
#pragma unroll
        for (int nt = 0; nt < 4; ++nt) {
            // ntile nt covers n offset (nt/2)*16 + (nt%2)*8
            const int col = nBase + wn + (nt >> 1) * 16 + (nt & 1) * 8 + c0;
            const float2 bb = *(const float2*)(be + col);
#pragma unroll
            for (int h = 0; h < 2; ++h) {
                const int row = mBase + wm + mi * 16 + r0 + h * 8;
                float v0 = fmaxf(acc[mi][nt][2 * h + 0] + bb.x, 0.f);
                float v1 = fmaxf(acc[mi][nt][2 * h + 1] + bb.y, 0.f);
                const size_t off = ((size_t)e * kB + row) * NTOT + col;
                if (SPLIT_OUT) {
                    __nv_bfloat16 h0 = __float2bfloat16(v0);
                    __nv_bfloat16 h1 = __float2bfloat16(v1);
                    __nv_bfloat162 hv; hv.x = h0; hv.y = h1;
                    __nv_bfloat162 lv;
                    lv.x = __float2bfloat16(v0 - __bfloat162float(h0));
                    lv.y = __float2bfloat16(v1 - __bfloat162float(h1));
                    *(__nv_bfloat162*)(Chi + off) = hv;
                    *(__nv_bfloat162*)(Clo + off) = lv;
                } else {
                    float2 o; o.x = v0; o.y = v1;
                    *(float2*)(Cf + off) = o;
                }
            }
        }
    }
}

// =====================================================================
// Expert layer 3: eo[e,b,:] = H2[e,b,:] @ Ew3[e] + Eb3[e]   (K=128, N=10)
// =====================================================================
__global__ __launch_bounds__(256)
void expert_l3_kernel(const float* __restrict__ Ew3, const float* __restrict__ Eb3)
{
    const int e = blockIdx.y;
    __shared__ float Ws[kEH2 * kEO];
    __shared__ float bs[kEO];
    for (int i = threadIdx.x; i < kEH2 * kEO; i += 256)
        Ws[i] = Ew3[(size_t)e * kEH2 * kEO + i];
    if (threadIdx.x < kEO) bs[threadIdx.x] = Eb3[e * kEO + threadIdx.x];
    __syncthreads();

    const int warp = threadIdx.x >> 5;
    const int lane = threadIdx.x & 31;
    const int b    = blockIdx.x * 8 + warp;

    const float* h = g_H2 + ((size_t)e * kB + b) * kEH2;
    float4 hv = *(const float4*)(h + lane * 4);

    float o[kEO];
#pragma unroll
    for (int j = 0; j < kEO; ++j) {
        o[j] = hv.x * Ws[(lane * 4 + 0) * kEO + j]
             + hv.y * Ws[(lane * 4 + 1) * kEO + j]
             + hv.z * Ws[(lane * 4 + 2) * kEO + j]
             + hv.w * Ws[(lane * 4 + 3) * kEO + j];
    }
#pragma unroll
    for (int j = 0; j < kEO; ++j)
#pragma unroll
        for (int off = 16; off; off >>= 1)
            o[j] += __shfl_xor_sync(0xffffffffu, o[j], off);

#pragma unroll
    for (int j = 0; j < kEO; ++j)
        if (lane == j)
            g_EO[((size_t)e * kB + b) * kEO + j] = o[j] + bs[j];
}

// =====================================================================
// Fused selected-domain gate + MMoE + tower. One warp per sample.
// Each lane owns outputs n=2*lane, 2*lane+1 (float2 weight loads).
// =====================================================================
__global__ __launch_bounds__(256)
void fused_gate_tower(const float* __restrict__ x, const int* __restrict__ dom,
                      const float* __restrict__ Gw1, const float* __restrict__ Gb1,
                      const float* __restrict__ Gw2, const float* __restrict__ Gb2,
                      const float* __restrict__ Tw1, const float* __restrict__ Tb1,
                      const float* __restrict__ Tw2, const float* __restrict__ Tb2,
                      float* __restrict__ out)
{
    const int warp = threadIdx.x >> 5;
    const int lane = threadIdx.x & 31;
    const int b    = blockIdx.x * 8 + warp;
    const int d    = dom[b];
    const int n0   = 2 * lane;

    // ---- gate hidden: this lane accumulates outputs n0, n0+1 ----
    const float* xr = x + (size_t)b * kIN;
    const float* W1 = Gw1 + (size_t)d * kIN * kGH;
    float acc0 = 0.f, acc1 = 0.f;
    for (int k0 = 0; k0 < kIN; k0 += 128) {
        float4 xv = *(const float4*)(xr + k0 + lane * 4);
#pragma unroll
        for (int kk = 0; kk < 32; ++kk) {
            const float* wb = W1 + (size_t)(k0 + kk * 4) * kGH + n0;
            float xs; float2 wv;
            xs = __shfl_sync(0xffffffffu, xv.x, kk);
            wv = *(const float2*)(wb);
            acc0 = fmaf(xs, wv.x, acc0); acc1 = fmaf(xs, wv.y, acc1);
            xs = __shfl_sync(0xffffffffu, xv.y, kk);
            wv = *(const float2*)(wb + kGH);
            acc0 = fmaf(xs, wv.x, acc0); acc1 = fmaf(xs, wv.y, acc1);
            xs = __shfl_sync(0xffffffffu, xv.z, kk);
            wv = *(const float2*)(wb + 2 * kGH);
            acc0 = fmaf(xs, wv.x, acc0); acc1 = fmaf(xs, wv.y, acc1);
            xs = __shfl_sync(0xffffffffu, xv.w, kk);
            wv = *(const float2*)(wb + 3 * kGH);
            acc0 = fmaf(xs, wv.x, acc0); acc1 = fmaf(xs, wv.y, acc1);
        }
    }
    float2 gb = *(const float2*)(Gb1 + d * kGH + n0);
    float g0 = fmaxf(acc0 + gb.x, 0.f);
    float g1 = fmaxf(acc1 + gb.y, 0.f);

    // ---- gate logits[6] + softmax ----
    float logit[kE];
#pragma unroll
    for (int e = 0; e < kE; ++e)
        logit[e] = g0 * Gw2[((size_t)d * kGH + n0) * kE + e]
                 + g1 * Gw2[((size_t)d * kGH + n0 + 1) * kE + e];
#pragma unroll
    for (int e = 0; e < kE; ++e)
#pragma unroll
        for (int off = 16; off; off >>= 1)
            logit[e] += __shfl_xor_sync(0xffffffffu, logit[e], off);

    float mx = -1e30f;
#pragma unroll
    for (int e = 0; e < kE; ++e) {
        logit[e] += Gb2[d * kE + e];
        mx = fmaxf(mx, logit[e]);
    }
    float se = 0.f;
    float gw[kE];
#pragma unroll
    for (int e = 0; e < kE; ++e) { gw[e] = expf(logit[e] - mx); se += gw[e]; }
    float inv = 1.f / se;

    // ---- eo gather: avg over experts + MMoE combine ----
    float mmoe = 0.f;
    if (lane < kEO) {
        float avg = 0.f;
#pragma unroll
        for (int e = 0; e < kE; ++e) {
            float v = g_EO[((size_t)e * kB + b) * kEO + lane];
            avg += v;
            mmoe = fmaf(gw[e] * inv, v, mmoe);
        }
        out[kB + (size_t)b * kEO + lane] = avg * (1.f / 6.f);
        out[kB + (size_t)kB * kEO + (size_t)b * kEO + lane] = mmoe;
    }

    float mm[kEO];
#pragma unroll
    for (int o = 0; o < kEO; ++o)
        mm[o] = __shfl_sync(0xffffffffu, mmoe, o);

    // ---- tower ----
    float2 tb = *(const float2*)(Tb1 + d * 64 + n0);
    float th0 = tb.x, th1 = tb.y;
#pragma unroll
    for (int o = 0; o < kEO; ++o) {
        float2 tw = *(const float2*)(Tw1 + ((size_t)d * kEO + o) * 64 + n0);
        th0 = fmaf(mm[o], tw.x, th0);
        th1 = fmaf(mm[o], tw.y, th1);
    }
    th0 = fmaxf(th0, 0.f);
    th1 = fmaxf(th1, 0.f);

    float2 t2 = *(const float2*)(Tw2 + d * 64 + n0);
    float s = th0 * t2.x + th1 * t2.y;
#pragma unroll
    for (int off = 16; off; off >>= 1)
        s += __shfl_xor_sync(0xffffffffu, s, off);

    if (lane == 0) {
        float z = s + Tb2[d];
        out[b] = 1.f / (1.f + expf(-z));
    }
}

// =====================================================================
// launch
// =====================================================================
extern "C" void kernel_launch(void* const* d_in, const int* in_sizes, int n_in,
                              void* d_out, int out_size)
{
    const float* x   = (const float*)d_in[0];
    const int*   dom = (const int*)  d_in[1];
    const float* Ew1 = (const float*)d_in[2];
    const float* Eb1 = (const float*)d_in[3];
    const float* Ew2 = (const float*)d_in[4];
    const float* Eb2 = (const float*)d_in[5];
    const float* Ew3 = (const float*)d_in[6];
    const float* Eb3 = (const float*)d_in[7];
    const float* Gw1 = (const float*)d_in[8];
    const float* Gb1 = (const float*)d_in[9];
    const float* Gw2 = (const float*)d_in[10];
    const float* Gb2 = (const float*)d_in[11];
    const float* Tw1 = (const float*)d_in[12];
    const float* Tb1 = (const float*)d_in[13];
    const float* Tw2 = (const float*)d_in[14];
    const float* Tb2 = (const float*)d_in[15];
    float* out = (float*)d_out;

    __nv_bfloat16 *Xhi, *Xlo, *W1hi, *W1lo, *W2hi, *W2lo, *H1hi, *H1lo;
    float *H2;
    cudaGetSymbolAddress((void**)&Xhi,  g_Xhi);
    cudaGetSymbolAddress((void**)&Xlo,  g_Xlo);
    cudaGetSymbolAddress((void**)&W1hi, g_W1hi);
    cudaGetSymbolAddress((void**)&W1lo, g_W1lo);
    cudaGetSymbolAddress((void**)&W2hi, g_W2hi);
    cudaGetSymbolAddress((void**)&W2lo, g_W2lo);
    cudaGetSymbolAddress((void**)&H1hi, g_H1hi);
    cudaGetSymbolAddress((void**)&H1lo, g_H1lo);
    cudaGetSymbolAddress((void**)&H2,   g_H2);

    constexpr int SMEM = 2 * (2 * 128 * 80 + 2 * 64 * 80);   // 61440
    cudaFuncSetAttribute(mma_gemm<kEH1, kIN, true>,
                         cudaFuncAttributeMaxDynamicSharedMemorySize, SMEM);
    cudaFuncSetAttribute(mma_gemm<kEH2, kEH1, false>,
                         cudaFuncAttributeMaxDynamicSharedMemorySize, SMEM);

    // --- prep: split x, transpose+split W1/W2 ---
    split_x_kernel<<<(kB * kIN / 4) / 256, 256>>>(
        (const float4*)x, (__nv_bfloat162*)Xhi, (__nv_bfloat162*)Xlo);
    transpose_split_kernel<<<dim3(kIN / 32, kEH1 / 32, kE), dim3(32, 8)>>>(
        Ew1, W1hi, W1lo, kIN, kEH1);
    transpose_split_kernel<<<dim3(kEH1 / 32, kEH2 / 32, kE), dim3(32, 8)>>>(
        Ew2, W2hi, W2lo, kEH1, kEH2);

    // --- expert L1 (HMMA): H1 = relu(x @ Ew1 + b), bf16 hi/lo out ---
    mma_gemm<kEH1, kIN, true><<<dim3(kEH1 / 64, kB / 128, kE), 256, SMEM>>>(
        Xhi, Xlo, W1hi, W1lo, Eb1, /*aStride=*/0,
        nullptr, H1hi, H1lo);

    // --- expert L2 (HMMA): H2 = relu(H1 @ Ew2 + b), fp32 out ---
    mma_gemm<kEH2, kEH1, false><<<dim3(kEH2 / 64, kB / 128, kE), 256, SMEM>>>(
        H1hi, H1lo, W2hi, W2lo, Eb2, /*aStride=*/(size_t)kB * kEH1,
        H2, nullptr, nullptr);

    // --- expert L3 (K=128, N=10) ---
    expert_l3_kernel<<<dim3(kB / 8, kE), 256>>>(Ew3, Eb3);

    // --- selected-domain gate + MMoE + tower + outputs ---
    fused_gate_tower<<<kB / 8, 256>>>(x, dom, Gw1, Gb1, Gw2, Gb2,
                                      Tw1, Tb1, Tw2, Tb2, out);
}

// round 12
// speedup vs baseline: 1.9594x; 1.0970x over previous
#include <cuda_runtime.h>
#include <cuda_bf16.h>
#include <math.h>
#include <stdint.h>

// ---------------- problem constants ----------------
constexpr int kB   = 16384;
constexpr int kIN  = 1024;
constexpr int kE   = 6;
constexpr int kD   = 20;
constexpr int kEH1 = 256;
constexpr int kEH2 = 128;
constexpr int kEO  = 10;
constexpr int kGH  = 64;

// ---------------- scratch (device globals: no allocs allowed) ----------------
__device__ __nv_bfloat16 g_Xhi[(size_t)kB * kIN];
__device__ __nv_bfloat16 g_Xlo[(size_t)kB * kIN];
__device__ __nv_bfloat16 g_W1hi[(size_t)kE * kEH1 * kIN];   // [E][N=256][K=1024] (transposed)
__device__ __nv_bfloat16 g_W1lo[(size_t)kE * kEH1 * kIN];
__device__ __nv_bfloat16 g_W2hi[(size_t)kE * kEH2 * kEH1];  // [E][N=128][K=256]
__device__ __nv_bfloat16 g_W2lo[(size_t)kE * kEH2 * kEH1];
__device__ __nv_bfloat16 g_H1hi[(size_t)kE * kB * kEH1];    // relu(L1) split
__device__ __nv_bfloat16 g_H1lo[(size_t)kE * kB * kEH1];
__device__ float g_H2[(size_t)kE * kB * kEH2];              // relu(L2) fp32
__device__ float g_EO[(size_t)kE * kB * kEO];               // L3 out

// domain bucketing scratch
__device__ int g_cnt[kD];
__device__ int g_off[kD];
__device__ int g_cur[kD];
__device__ int g_order[kB];

// =====================================================================
// PTX helpers (sm_80-era ISA only — harness targets plain sm_103)
// =====================================================================
__device__ __forceinline__ uint32_t smem_u32(const void* p) {
    return (uint32_t)__cvta_generic_to_shared(p);
}
__device__ __forceinline__ void cp_async16(uint32_t dst, const void* src) {
    asm volatile("cp.async.cg.shared.global [%0], [%1], 16;" :: "r"(dst), "l"(src));
}
__device__ __forceinline__ void cp_commit() { asm volatile("cp.async.commit_group;" ::: "memory"); }
__device__ __forceinline__ void cp_wait1()  { asm volatile("cp.async.wait_group 1;" ::: "memory"); }

__device__ __forceinline__ void ldsm4(uint32_t& r0, uint32_t& r1, uint32_t& r2, uint32_t& r3,
                                      uint32_t addr) {
    asm volatile("ldmatrix.sync.aligned.m8n8.x4.shared.b16 {%0,%1,%2,%3}, [%4];"
                 : "=r"(r0), "=r"(r1), "=r"(r2), "=r"(r3) : "r"(addr));
}
__device__ __forceinline__ void mma16816(float* c, const uint32_t* a, uint32_t b0, uint32_t b1) {
    asm volatile("mma.sync.aligned.m16n8k16.row.col.f32.bf16.bf16.f32 "
                 "{%0,%1,%2,%3},{%4,%5,%6,%7},{%8,%9},{%0,%1,%2,%3};"
                 : "+f"(c[0]), "+f"(c[1]), "+f"(c[2]), "+f"(c[3])
                 : "r"(a[0]), "r"(a[1]), "r"(a[2]), "r"(a[3]), "r"(b0), "r"(b1));
}

// =====================================================================
// Prep: split x into bf16 hi/lo
// =====================================================================
__global__ __launch_bounds__(256)
void split_x_kernel(const float4* __restrict__ x,
                    __nv_bfloat162* __restrict__ hi, __nv_bfloat162* __restrict__ lo)
{
    size_t i = (size_t)blockIdx.x * 256 + threadIdx.x;
    float4 v = x[i];
    __nv_bfloat16 hx = __float2bfloat16(v.x), hy = __float2bfloat16(v.y);
    __nv_bfloat16 hz = __float2bfloat16(v.z), hw = __float2bfloat16(v.w);
    __nv_bfloat162 H0; H0.x = hx; H0.y = hy;
    __nv_bfloat162 H1; H1.x = hz; H1.y = hw;
    __nv_bfloat162 L0, L1;
    L0.x = __float2bfloat16(v.x - __bfloat162float(hx));
    L0.y = __float2bfloat16(v.y - __bfloat162float(hy));
    L1.x = __float2bfloat16(v.z - __bfloat162float(hz));
    L1.y = __float2bfloat16(v.w - __bfloat162float(hw));
    hi[2 * i] = H0; hi[2 * i + 1] = H1;
    lo[2 * i] = L0; lo[2 * i + 1] = L1;
}

// =====================================================================
// Prep: W [E][K][N] fp32 -> Wt hi/lo bf16 [E][N][K]
// =====================================================================
__global__ __launch_bounds__(256)
void transpose_split_kernel(const float* __restrict__ W,
                            __nv_bfloat16* __restrict__ hi, __nv_bfloat16* __restrict__ lo,
                            int K, int N)
{
    __shared__ float t[32][33];
    const int e = blockIdx.z;
    const float* We = W + (size_t)e * K * N;
    const int k0 = blockIdx.x * 32, n0 = blockIdx.y * 32;
    const int tx = threadIdx.x, ty = threadIdx.y;
    for (int i = ty; i < 32; i += 8)
        t[i][tx] = We[(size_t)(k0 + i) * N + n0 + tx];
    __syncthreads();
    for (int i = ty; i < 32; i += 8) {
        float v = t[tx][i];  // = W[k0+tx][n0+i]
        size_t o = ((size_t)e * N + n0 + i) * K + k0 + tx;
        __nv_bfloat16 h = __float2bfloat16(v);
        hi[o] = h;
        lo[o] = __float2bfloat16(v - __bfloat162float(h));
    }
}

// =====================================================================
// mma.sync split-bf16 GEMM, CTA tile 128x128, BK=32, 2-stage cp.async.
// 8 warps (4m x 2n), warp tile 32x64 -> 4 MMAs per ldmatrix.
// D += Ahi*Bhi + Alo*Bhi + Ahi*Blo (fp32 reg accumulate)
// =====================================================================
template<int NTOT, int KTOT, bool SPLIT_OUT>
__global__ __launch_bounds__(256, 2)
void mma_gemm(const __nv_bfloat16* __restrict__ Ahb, const __nv_bfloat16* __restrict__ Alb,
              const __nv_bfloat16* __restrict__ Bh_all, const __nv_bfloat16* __restrict__ Bl_all,
              const float* __restrict__ bias, size_t aStride,
              float* __restrict__ Cf, __nv_bfloat16* __restrict__ Chi,
              __nv_bfloat16* __restrict__ Clo)
{
    constexpr int BK = 32;
    constexpr int NCHUNK = KTOT / BK;
    constexpr int ROWB = 80;                 // 64B data + 16B pad
    constexpr int T_SZ = 128 * ROWB;         // 10240 per hi/lo tile (A and B both 128 rows)
    constexpr int STAGE = 4 * T_SZ;          // 40960

    extern __shared__ char dsm[];
    const uint32_t sb = smem_u32(dsm);

    const int tid  = threadIdx.x;
    const int w    = tid >> 5;
    const int lane = tid & 31;
    const int e     = blockIdx.z;
    const int mBase = blockIdx.y * 128;
    const int nBase = blockIdx.x * 128;
    const int wm = (w & 3) * 32;
    const int wn = (w >> 2) * 64;

    const __nv_bfloat16* Ah = Ahb + (size_t)e * aStride;
    const __nv_bfloat16* Al = Alb + (size_t)e * aStride;
    const __nv_bfloat16* Bh = Bh_all + (size_t)e * NTOT * KTOT;
    const __nv_bfloat16* Bl = Bl_all + (size_t)e * NTOT * KTOT;

    auto load_chunk = [&](int c, int s) {
        const uint32_t st = sb + s * STAGE;
        // seg 0: A-hi, 1: A-lo, 2: B-hi, 3: B-lo ; each 128 rows x 4 granules
#pragma unroll
        for (int g = tid; g < 2048; g += 256) {
            const int seg = g >> 9;
            const int idx = g & 511;
            const int row = idx >> 2, gr = idx & 3;
            const __nv_bfloat16* base =
                (seg == 0) ? Ah : (seg == 1) ? Al : (seg == 2) ? Bh : Bl;
            const size_t grow = (seg < 2) ? (size_t)(mBase + row) : (size_t)(nBase + row);
            cp_async16(st + seg * T_SZ + row * ROWB + gr * 16,
                       base + grow * KTOT + c * BK + gr * 8);
        }
    };

    float acc[2][8][4];
#pragma unroll
    for (int i = 0; i < 2; ++i)
#pragma unroll
        for (int j = 0; j < 8; ++j)
#pragma unroll
            for (int q = 0; q < 4; ++q) acc[i][j][q] = 0.f;

    load_chunk(0, 0); cp_commit();
    load_chunk(1, 1); cp_commit();

    const int lr = lane & 15;
    const int lc = (lane >> 4) * 16;   // byte offset of 8-col half

    for (int i = 0; i < NCHUNK; ++i) {
        const int s = i & 1;
        cp_wait1();
        __syncthreads();
        const uint32_t st     = sb + s * STAGE;
        const uint32_t aBaseH = st + wm * ROWB;
        const uint32_t aBaseL = aBaseH + T_SZ;
        const uint32_t bBaseH = st + 2 * T_SZ + wn * ROWB;
        const uint32_t bBaseL = bBaseH + T_SZ;

#pragma unroll
        for (int ks = 0; ks < 2; ++ks) {
            const uint32_t koff = ks * 32 + lc;
            uint32_t ah[2][4], bh[4][4];
#pragma unroll
            for (int mi = 0; mi < 2; ++mi)
                ldsm4(ah[mi][0], ah[mi][1], ah[mi][2], ah[mi][3],
                      aBaseH + (mi * 16 + lr) * ROWB + koff);
#pragma unroll
            for (int nj = 0; nj < 4; ++nj)
                ldsm4(bh[nj][0], bh[nj][1], bh[nj][2], bh[nj][3],
                      bBaseH + (nj * 16 + lr) * ROWB + koff);
            // term 1: Ahi * Bhi
#pragma unroll
            for (int mi = 0; mi < 2; ++mi)
#pragma unroll
                for (int nj = 0; nj < 4; ++nj)
#pragma unroll
                    for (int t = 0; t < 2; ++t)
                        mma16816(acc[mi][nj * 2 + t], ah[mi], bh[nj][t], bh[nj][t + 2]);
            // term 2: Alo * Bhi
            {
                uint32_t al[2][4];
#pragma unroll
                for (int mi = 0; mi < 2; ++mi)
                    ldsm4(al[mi][0], al[mi][1], al[mi][2], al[mi][3],
                          aBaseL + (mi * 16 + lr) * ROWB + koff);
#pragma unroll
                for (int mi = 0; mi < 2; ++mi)
#pragma unroll
                    for (int nj = 0; nj < 4; ++nj)
#pragma unroll
                        for (int t = 0; t < 2; ++t)
                            mma16816(acc[mi][nj * 2 + t], al[mi], bh[nj][t], bh[nj][t + 2]);
            }
            // term 3: Ahi * Blo
            {
                uint32_t bl[4][4];
#pragma unroll
                for (int nj = 0; nj < 4; ++nj)
                    ldsm4(bl[nj][0], bl[nj][1], bl[nj][2], bl[nj][3],
                          bBaseL + (nj * 16 + lr) * ROWB + koff);
#pragma unroll
                for (int mi = 0; mi < 2; ++mi)
#pragma unroll
                    for (int nj = 0; nj < 4; ++nj)
#pragma unroll
                        for (int t = 0; t < 2; ++t)
                            mma16816(acc[mi][nj * 2 + t], ah[mi], bl[nj][t], bl[nj][t + 2]);
            }
        }
        __syncthreads();
        if (i + 2 < NCHUNK) load_chunk(i + 2, s);
        cp_commit();
    }

    // ---- epilogue: bias + relu, store ----
    const float* be = bias + e * NTOT;
    const int r0 = lane >> 2;
    const int c0 = (lane & 3) * 2;
#pragma unroll
    for (int mi = 0; mi < 2; ++mi) {
#pragma unroll
        for (int nt = 0; nt < 8; ++nt) {
            const int col = nBase + wn + (nt >> 1) * 16 + (nt & 1) * 8 + c0;
            const float2 bb = *(const float2*)(be + col);
#pragma unroll
            for (int h = 0; h < 2; ++h) {
                const int row = mBase + wm + mi * 16 + r0 + h * 8;
                float v0 = fmaxf(acc[mi][nt][2 * h + 0] + bb.x, 0.f);
                float v1 = fmaxf(acc[mi][nt][2 * h + 1] + bb.y, 0.f);
                const size_t off = ((size_t)e * kB + row) * NTOT + col;
                if (SPLIT_OUT) {
                    __nv_bfloat16 h0 = __float2bfloat16(v0);
                    __nv_bfloat16 h1 = __float2bfloat16(v1);
                    __nv_bfloat162 hv; hv.x = h0; hv.y = h1;
                    __nv_bfloat162 lv;
                    lv.x = __float2bfloat16(v0 - __bfloat162float(h0));
                    lv.y = __float2bfloat16(v1 - __bfloat162float(h1));
                    *(__nv_bfloat162*)(Chi + off) = hv;
                    *(__nv_bfloat162*)(Clo + off) = lv;
                } else {
                    float2 o; o.x = v0; o.y = v1;
                    *(float2*)(Cf + off) = o;
                }
            }
        }
    }
}

// =====================================================================
// Expert layer 3: eo[e,b,:] = H2[e,b,:] @ Ew3[e] + Eb3[e]   (K=128, N=10)
// =====================================================================
__global__ __launch_bounds__(256)
void expert_l3_kernel(const float* __restrict__ Ew3, const float* __restrict__ Eb3)
{
    const int e = blockIdx.y;
    __shared__ float Ws[kEH2 * kEO];
    __shared__ float bs[kEO];
    for (int i = threadIdx.x; i < kEH2 * kEO; i += 256)
        Ws[i] = Ew3[(size_t)e * kEH2 * kEO + i];
    if (threadIdx.x < kEO) bs[threadIdx.x] = Eb3[e * kEO + threadIdx.x];
    __syncthreads();

    const int warp = threadIdx.x >> 5;
    const int lane = threadIdx.x & 31;
    const int b    = blockIdx.x * 8 + warp;

    const float* h = g_H2 + ((size_t)e * kB + b) * kEH2;
    float4 hv = *(const float4*)(h + lane * 4);

    float o[kEO];
#pragma unroll
    for (int j = 0; j < kEO; ++j) {
        o[j] = hv.x * Ws[(lane * 4 + 0) * kEO + j]
             + hv.y * Ws[(lane * 4 + 1) * kEO + j]
             + hv.z * Ws[(lane * 4 + 2) * kEO + j]
             + hv.w * Ws[(lane * 4 + 3) * kEO + j];
    }
#pragma unroll
    for (int j = 0; j < kEO; ++j)
#pragma unroll
        for (int off = 16; off; off >>= 1)
            o[j] += __shfl_xor_sync(0xffffffffu, o[j], off);

#pragma unroll
    for (int j = 0; j < kEO; ++j)
        if (lane == j)
            g_EO[((size_t)e * kB + b) * kEO + j] = o[j] + bs[j];
}

// =====================================================================
// Domain bucketing (tiny kernels). Order within a bucket is atomic-
// nondeterministic but per-sample results are order-independent.
// =====================================================================
__global__ void bucket_zero() {
    if (threadIdx.x < kD) { g_cnt[threadIdx.x] = 0; g_cur[threadIdx.x] = 0; }
}
__global__ __launch_bounds__(256)
void bucket_count(const int* __restrict__ dom) {
    int i = blockIdx.x * 256 + threadIdx.x;
    atomicAdd(&g_cnt[dom[i]], 1);
}
__global__ void bucket_scan() {
    if (threadIdx.x == 0) {
        int a = 0;
        for (int d = 0; d < kD; ++d) { g_off[d] = a; a += g_cnt[d]; }
    }
}
__global__ __launch_bounds__(256)
void bucket_scatter(const int* __restrict__ dom) {
    int i = blockIdx.x * 256 + threadIdx.x;
    int d = dom[i];
    int p = atomicAdd(&g_cur[d], 1);
    g_order[g_off[d] + p] = i;
}

// =====================================================================
// Bucketed gate + MMoE + tower. Each block serves up to 64 samples of
// ONE domain; Gw1[d] K-chunks staged through smem (reuse x64).
// =====================================================================
constexpr int NS  = 64;   // samples per block-chunk
constexpr int GCH = 16;   // grid.x stride over chunks

__global__ __launch_bounds__(256)
void gate_tower_bucketed(const float* __restrict__ x,
                         const float* __restrict__ Gw1, const float* __restrict__ Gb1,
                         const float* __restrict__ Gw2, const float* __restrict__ Gb2,
                         const float* __restrict__ Tw1, const float* __restrict__ Tb1,
                         const float* __restrict__ Tw2, const float* __restrict__ Tb2,
                         float* __restrict__ out)
{
    __shared__ int   sid[NS];
    __shared__ float Ws[64 * 64];    // Gw1 chunk [k 64][n 64]
    __shared__ float Xs[NS * 64];    // x chunk; reused for gate hidden at the end

    const int d    = blockIdx.y;
    const int cnt  = g_cnt[d];
    const int off  = g_off[d];
    const int tid  = threadIdx.x;
    const int w    = tid >> 5;
    const int lane = tid & 31;
    const int n0   = 2 * lane;

    for (int chunk = blockIdx.x; chunk * NS < cnt; chunk += GCH) {
        const int base = off + chunk * NS;
        const int ns   = min(NS, cnt - chunk * NS);
        if (tid < NS) sid[tid] = (tid < ns) ? g_order[base + tid] : -1;
        __syncthreads();

        // ---- gate hidden GEMM: acc[s8][0..1] = x[s] . Gw1[d][:, n0..n0+1] ----
        float acc[8][2];
#pragma unroll
        for (int s8 = 0; s8 < 8; ++s8) { acc[s8][0] = 0.f; acc[s8][1] = 0.f; }

        const float* W1 = Gw1 + (size_t)d * kIN * kGH;
        for (int k0 = 0; k0 < kIN; k0 += 64) {
            for (int i = tid; i < 64 * 16; i += 256) {
                int r = i >> 4, c4 = (i & 15) * 4;
                *(float4*)&Ws[r * 64 + c4] = *(const float4*)(W1 + (size_t)(k0 + r) * kGH + c4);
            }
            for (int i = tid; i < NS * 16; i += 256) {
                int slot = i >> 4, c4 = (i & 15) * 4;
                int s = sid[slot];
                float4 v = (s >= 0) ? *(const float4*)(x + (size_t)s * kIN + k0 + c4)
                                    : make_float4(0.f, 0.f, 0.f, 0.f);
                *(float4*)&Xs[slot * 64 + c4] = v;
            }
            __syncthreads();
#pragma unroll 4
            for (int kk = 0; kk < 64; ++kk) {
                float2 wv = *(const float2*)&Ws[kk * 64 + n0];
#pragma unroll
                for (int s8 = 0; s8 < 8; ++s8) {
                    float xv = Xs[(w * 8 + s8) * 64 + kk];
                    acc[s8][0] = fmaf(xv, wv.x, acc[s8][0]);
                    acc[s8][1] = fmaf(xv, wv.y, acc[s8][1]);
                }
            }
            __syncthreads();
        }

        // bias + relu -> gate hidden into Xs
        float2 gb = *(const float2*)(Gb1 + d * kGH + n0);
#pragma unroll
        for (int s8 = 0; s8 < 8; ++s8) {
            int slot = w * 8 + s8;
            Xs[slot * 64 + n0]     = fmaxf(acc[s8][0] + gb.x, 0.f);
            Xs[slot * 64 + n0 + 1] = fmaxf(acc[s8][1] + gb.y, 0.f);
        }
        __syncthreads();

        // ---- tail: one warp per sample slot ----
        for (int slot = w; slot < NS; slot += 8) {
            const int b = sid[slot];
            if (b < 0) continue;
            float g0 = Xs[slot * 64 + lane];
            float g1 = Xs[slot * 64 + lane + 32];

            float logit[kE];
#pragma unroll
            for (int e = 0; e < kE; ++e)
                logit[e] = g0 * Gw2[((size_t)d * kGH + lane) * kE + e]
                         + g1 * Gw2[((size_t)d * kGH + lane + 32) * kE + e];
#pragma unroll
            for (int e = 0; e < kE; ++e)
#pragma unroll
                for (int o = 16; o; o >>= 1)
                    logit[e] += __shfl_xor_sync(0xffffffffu, logit[e], o);

            float mx = -1e30f;
#pragma unroll
            for (int e = 0; e < kE; ++e) {
                logit[e] += Gb2[d * kE + e];
                mx = fmaxf(mx, logit[e]);
            }
            float se = 0.f, gw[kE];
#pragma unroll
            for (int e = 0; e < kE; ++e) { gw[e] = expf(logit[e] - mx); se += gw[e]; }
            float inv = 1.f / se;

            float mmoe = 0.f;
            if (lane < kEO) {
                float avg = 0.f;
#pragma unroll
                for (int e = 0; e < kE; ++e) {
                    float v = g_EO[((size_t)e * kB + b) * kEO + lane];
                    avg += v;
                    mmoe = fmaf(gw[e] * inv, v, mmoe);
                }
                out[kB + (size_t)b * kEO + lane] = avg * (1.f / 6.f);
                out[kB + (size_t)kB * kEO + (size_t)b * kEO + lane] = mmoe;
            }

            float mm[kEO];
#pragma unroll
            for (int o = 0; o < kEO; ++o)
                mm[o] = __shfl_sync(0xffffffffu, mmoe, o);

            float th0 = Tb1[d * 64 + lane];
            float th1 = Tb1[d * 64 + lane + 32];
#pragma unroll
            for (int o = 0; o < kEO; ++o) {
                th0 = fmaf(mm[o], Tw1[((size_t)d * kEO + o) * 64 + lane],      th0);
                th1 = fmaf(mm[o], Tw1[((size_t)d * kEO + o) * 64 + lane + 32], th1);
            }
            th0 = fmaxf(th0, 0.f);
            th1 = fmaxf(th1, 0.f);

            float s = th0 * Tw2[d * 64 + lane] + th1 * Tw2[d * 64 + lane + 32];
#pragma unroll
            for (int o = 16; o; o >>= 1)
                s += __shfl_xor_sync(0xffffffffu, s, o);

            if (lane == 0) {
                float z = s + Tb2[d];
                out[b] = 1.f / (1.f + expf(-z));
            }
        }
        __syncthreads();   // protect sid/Xs before next chunk
    }
}

// =====================================================================
// launch
// =====================================================================
extern "C" void kernel_launch(void* const* d_in, const int* in_sizes, int n_in,
                              void* d_out, int out_size)
{
    const float* x   = (const float*)d_in[0];
    const int*   dom = (const int*)  d_in[1];
    const float* Ew1 = (const float*)d_in[2];
    const float* Eb1 = (const float*)d_in[3];
    const float* Ew2 = (const float*)d_in[4];
    const float* Eb2 = (const float*)d_in[5];
    const float* Ew3 = (const float*)d_in[6];
    const float* Eb3 = (const float*)d_in[7];
    const float* Gw1 = (const float*)d_in[8];
    const float* Gb1 = (const float*)d_in[9];
    const float* Gw2 = (const float*)d_in[10];
    const float* Gb2 = (const float*)d_in[11];
    const float* Tw1 = (const float*)d_in[12];
    const float* Tb1 = (const float*)d_in[13];
    const float* Tw2 = (const float*)d_in[14];
    const float* Tb2 = (const float*)d_in[15];
    float* out = (float*)d_out;

    __nv_bfloat16 *Xhi, *Xlo, *W1hi, *W1lo, *W2hi, *W2lo, *H1hi, *H1lo;
    float *H2;
    cudaGetSymbolAddress((void**)&Xhi,  g_Xhi);
    cudaGetSymbolAddress((void**)&Xlo,  g_Xlo);
    cudaGetSymbolAddress((void**)&W1hi, g_W1hi);
    cudaGetSymbolAddress((void**)&W1lo, g_W1lo);
    cudaGetSymbolAddress((void**)&W2hi, g_W2hi);
    cudaGetSymbolAddress((void**)&W2lo, g_W2lo);
    cudaGetSymbolAddress((void**)&H1hi, g_H1hi);
    cudaGetSymbolAddress((void**)&H1lo, g_H1lo);
    cudaGetSymbolAddress((void**)&H2,   g_H2);

    constexpr int SMEM = 2 * 4 * 128 * 80;   // 81920 (2 stages x 4 tiles x 128 x 80B)
    cudaFuncSetAttribute(mma_gemm<kEH1, kIN, true>,
                         cudaFuncAttributeMaxDynamicSharedMemorySize, SMEM);
    cudaFuncSetAttribute(mma_gemm<kEH2, kEH1, false>,
                         cudaFuncAttributeMaxDynamicSharedMemorySize, SMEM);

    // --- bucketing (independent of expert path) ---
    bucket_zero<<<1, 32>>>();
    bucket_count<<<kB / 256, 256>>>(dom);
    bucket_scan<<<1, 32>>>();
    bucket_scatter<<<kB / 256, 256>>>(dom);

    // --- prep: split x, transpose+split W1/W2 ---
    split_x_kernel<<<(kB * kIN / 4) / 256, 256>>>(
        (const float4*)x, (__nv_bfloat162*)Xhi, (__nv_bfloat162*)Xlo);
    transpose_split_kernel<<<dim3(kIN / 32, kEH1 / 32, kE), dim3(32, 8)>>>(
        Ew1, W1hi, W1lo, kIN, kEH1);
    transpose_split_kernel<<<dim3(kEH1 / 32, kEH2 / 32, kE), dim3(32, 8)>>>(
        Ew2, W2hi, W2lo, kEH1, kEH2);

    // --- expert L1 (HMMA): H1 = relu(x @ Ew1 + b), bf16 hi/lo out ---
    mma_gemm<kEH1, kIN, true><<<dim3(kEH1 / 128, kB / 128, kE), 256, SMEM>>>(
        Xhi, Xlo, W1hi, W1lo, Eb1, /*aStride=*/0,
        nullptr, H1hi, H1lo);

    // --- expert L2 (HMMA): H2 = relu(H1 @ Ew2 + b), fp32 out ---
    mma_gemm<kEH2, kEH1, false><<<dim3(kEH2 / 128, kB / 128, kE), 256, SMEM>>>(
        H1hi, H1lo, W2hi, W2lo, Eb2, /*aStride=*/(size_t)kB * kEH1,
        H2, nullptr, nullptr);

    // --- expert L3 (K=128, N=10) ---
    expert_l3_kernel<<<dim3(kB / 8, kE), 256>>>(Ew3, Eb3);

    // --- bucketed gate + MMoE + tower + outputs ---
    gate_tower_bucketed<<<dim3(GCH, kD), 256>>>(x, Gw1, Gb1, Gw2, Gb2,
                                                Tw1, Tb1, Tw2, Tb2, out);
}

// round 13
// speedup vs baseline: 2.4592x; 1.2551x over previous
#include <cuda_runtime.h>
#include <cuda_fp16.h>
#include <math.h>
#include <stdint.h>

// ---------------- problem constants ----------------
constexpr int kB   = 16384;
constexpr int kIN  = 1024;
constexpr int kE   = 6;
constexpr int kD   = 20;
constexpr int kEH1 = 256;
constexpr int kEH2 = 128;
constexpr int kEO  = 10;
constexpr int kGH  = 64;

// ---------------- scratch (device globals: no allocs allowed) ----------------
__device__ __half g_Xhi[(size_t)kB * kIN];                 // fp16 hi of x
__device__ __half g_Xlo[(size_t)kB * kIN];                 // fp16 lo of x
__device__ __half g_W1h[(size_t)kE * kEH1 * kIN];          // [E][N=256][K=1024] fp16 (transposed)
__device__ __half g_W2h[(size_t)kE * kEH2 * kEH1];         // [E][N=128][K=256]  fp16
__device__ __half g_H1hi[(size_t)kE * kB * kEH1];          // relu(L1) fp16 hi
__device__ __half g_H1lo[(size_t)kE * kB * kEH1];          // relu(L1) fp16 lo
__device__ float  g_EO[(size_t)kE * kB * kEO];             // expert outputs

// domain bucketing scratch
__device__ int g_cnt[kD];
__device__ int g_off[kD];
__device__ int g_cur[kD];
__device__ int g_order[kB];

// =====================================================================
// PTX helpers (sm_80-era ISA — harness targets plain sm_103, no tcgen05)
// =====================================================================
__device__ __forceinline__ uint32_t smem_u32(const void* p) {
    return (uint32_t)__cvta_generic_to_shared(p);
}
__device__ __forceinline__ void cp_async16(uint32_t dst, const void* src) {
    asm volatile("cp.async.cg.shared.global [%0], [%1], 16;" :: "r"(dst), "l"(src));
}
__device__ __forceinline__ void cp_commit() { asm volatile("cp.async.commit_group;" ::: "memory"); }
__device__ __forceinline__ void cp_wait2()  { asm volatile("cp.async.wait_group 2;" ::: "memory"); }

__device__ __forceinline__ void ldsm4(uint32_t& r0, uint32_t& r1, uint32_t& r2, uint32_t& r3,
                                      uint32_t addr) {
    asm volatile("ldmatrix.sync.aligned.m8n8.x4.shared.b16 {%0,%1,%2,%3}, [%4];"
                 : "=r"(r0), "=r"(r1), "=r"(r2), "=r"(r3) : "r"(addr));
}
__device__ __forceinline__ void mma16816(float* c, const uint32_t* a, uint32_t b0, uint32_t b1) {
    asm volatile("mma.sync.aligned.m16n8k16.row.col.f32.f16.f16.f32 "
                 "{%0,%1,%2,%3},{%4,%5,%6,%7},{%8,%9},{%0,%1,%2,%3};"
                 : "+f"(c[0]), "+f"(c[1]), "+f"(c[2]), "+f"(c[3])
                 : "r"(a[0]), "r"(a[1]), "r"(a[2]), "r"(a[3]), "r"(b0), "r"(b1));
}

// =====================================================================
// Prep: split x into fp16 hi/lo  (x = hi + lo, |lo| <= 2^-11 |x|)
// =====================================================================
__global__ __launch_bounds__(256)
void split_x_kernel(const float4* __restrict__ x,
                    __half2* __restrict__ hi, __half2* __restrict__ lo)
{
    size_t i = (size_t)blockIdx.x * 256 + threadIdx.x;
    float4 v = x[i];
    __half hx = __float2half(v.x), hy = __float2half(v.y);
    __half hz = __float2half(v.z), hw = __float2half(v.w);
    __half2 H0; H0.x = hx; H0.y = hy;
    __half2 H1; H1.x = hz; H1.y = hw;
    __half2 L0, L1;
    L0.x = __float2half(v.x - __half2float(hx));
    L0.y = __float2half(v.y - __half2float(hy));
    L1.x = __float2half(v.z - __half2float(hz));
    L1.y = __float2half(v.w - __half2float(hw));
    hi[2 * i] = H0; hi[2 * i + 1] = H1;
    lo[2 * i] = L0; lo[2 * i + 1] = L1;
}

// =====================================================================
// Prep: W [E][K][N] fp32 -> W^T fp16 [E][N][K]
// =====================================================================
__global__ __launch_bounds__(256)
void transpose_h_kernel(const float* __restrict__ W, __half* __restrict__ hi,
                        int K, int N)
{
    __shared__ float t[32][33];
    const int e = blockIdx.z;
    const float* We = W + (size_t)e * K * N;
    const int k0 = blockIdx.x * 32, n0 = blockIdx.y * 32;
    const int tx = threadIdx.x, ty = threadIdx.y;
    for (int i = ty; i < 32; i += 8)
        t[i][tx] = We[(size_t)(k0 + i) * N + n0 + tx];
    __syncthreads();
    for (int i = ty; i < 32; i += 8) {
        size_t o = ((size_t)e * N + n0 + i) * K + k0 + tx;
        hi[o] = __float2half(t[tx][i]);   // = W[k0+tx][n0+i]
    }
}

// =====================================================================
// mma.sync fp16 split GEMM:
//   C[e][M,NTOT] = relu( A[e][M,KTOT] @ W[e][NTOT,KTOT]^T + bias[e] )
//   D = Ahi*Wh + Alo*Wh  (fp32 accumulate; A exact to ~2^-21, W to 2^-11)
// CTA 128x128, BK=32, 3-stage cp.async, 8 warps (4m x 2n), warp 32x64.
// SPLIT_OUT: emit fp16 hi/lo (feeds next layer).
// FUSE_L3:  stage H2 in smem, compute EO = H2 @ Ew3 + Eb3 in-kernel.
// =====================================================================
template<int NTOT, int KTOT, bool SPLIT_OUT, bool FUSE_L3>
__global__ __launch_bounds__(256, 2)
void mma_gemm(const __half* __restrict__ Ahb, const __half* __restrict__ Alb,
              const __half* __restrict__ Wh_all,
              const float* __restrict__ bias, size_t aStride,
              __half* __restrict__ Chi, __half* __restrict__ Clo,
              const float* __restrict__ Ew3, const float* __restrict__ Eb3)
{
    constexpr int BK = 32;
    constexpr int NCHUNK = KTOT / BK;
    constexpr int ROWB = 80;                 // 64B data + 16B pad (conflict-free ldsm)
    constexpr int T_SZ = 128 * ROWB;         // 10240 per tile
    constexpr int STAGE = 3 * T_SZ;          // A-hi, A-lo, W-hi = 30720
    // dynamic smem = 3 stages = 92160 (2 CTAs/SM -> 184320 <= 227KB)

    extern __shared__ char dsm[];
    const uint32_t sb = smem_u32(dsm);

    const int tid  = threadIdx.x;
    const int w    = tid >> 5;
    const int lane = tid & 31;
    const int e     = blockIdx.z;
    const int mBase = blockIdx.y * 128;
    const int nBase = blockIdx.x * 128;
    const int wm = (w & 3) * 32;
    const int wn = (w >> 2) * 64;

    const __half* Ah = Ahb + (size_t)e * aStride;
    const __half* Al = Alb + (size_t)e * aStride;
    const __half* Wh = Wh_all + (size_t)e * NTOT * KTOT;

    auto load_chunk = [&](int c, int s) {
        const uint32_t st = sb + s * STAGE;
        // seg 0: A-hi, 1: A-lo, 2: W-hi ; each 128 rows x 4 granules of 16B
#pragma unroll
        for (int g = tid; g < 1536; g += 256) {
            const int seg = g >> 9;
            const int idx = g & 511;
            const int row = idx >> 2, gr = idx & 3;
            const __half* base = (seg == 0) ? Ah : (seg == 1) ? Al : Wh;
            const size_t grow = (seg < 2) ? (size_t)(mBase + row) : (size_t)(nBase + row);
            cp_async16(st + seg * T_SZ + row * ROWB + gr * 16,
                       base + grow * KTOT + c * BK + gr * 8);
        }
    };

    float acc[2][8][4];
#pragma unroll
    for (int i = 0; i < 2; ++i)
#pragma unroll
        for (int j = 0; j < 8; ++j)
#pragma unroll
            for (int q = 0; q < 4; ++q) acc[i][j][q] = 0.f;

    load_chunk(0, 0); cp_commit();
    load_chunk(1, 1); cp_commit();
    load_chunk(2, 2); cp_commit();

    const int lr = lane & 15;
    const int lc = (lane >> 4) * 16;   // byte offset of 8-col half

    int s = 0;
    for (int i = 0; i < NCHUNK; ++i) {
        cp_wait2();
        __syncthreads();
        const uint32_t st     = sb + s * STAGE;
        const uint32_t aBaseH = st + wm * ROWB;
        const uint32_t aBaseL = aBaseH + T_SZ;
        const uint32_t bBaseH = st + 2 * T_SZ + wn * ROWB;

#pragma unroll
        for (int ks = 0; ks < 2; ++ks) {
            const uint32_t koff = ks * 32 + lc;
            uint32_t ah[2][4], bh[4][4];
#pragma unroll
            for (int mi = 0; mi < 2; ++mi)
                ldsm4(ah[mi][0], ah[mi][1], ah[mi][2], ah[mi][3],
                      aBaseH + (mi * 16 + lr) * ROWB + koff);
#pragma unroll
            for (int nj = 0; nj < 4; ++nj)
                ldsm4(bh[nj][0], bh[nj][1], bh[nj][2], bh[nj][3],
                      bBaseH + (nj * 16 + lr) * ROWB + koff);
            // term 1: Ahi * Wh
#pragma unroll
            for (int mi = 0; mi < 2; ++mi)
#pragma unroll
                for (int nj = 0; nj < 4; ++nj)
#pragma unroll
                    for (int t = 0; t < 2; ++t)
                        mma16816(acc[mi][nj * 2 + t], ah[mi], bh[nj][t], bh[nj][t + 2]);
            // term 2: Alo * Wh
            {
                uint32_t al[2][4];
#pragma unroll
                for (int mi = 0; mi < 2; ++mi)
                    ldsm4(al[mi][0], al[mi][1], al[mi][2], al[mi][3],
                          aBaseL + (mi * 16 + lr) * ROWB + koff);
#pragma unroll
                for (int mi = 0; mi < 2; ++mi)
#pragma unroll
                    for (int nj = 0; nj < 4; ++nj)
#pragma unroll
                        for (int t = 0; t < 2; ++t)
                            mma16816(acc[mi][nj * 2 + t], al[mi], bh[nj][t], bh[nj][t + 2]);
            }
        }
        __syncthreads();
        if (i + 3 < NCHUNK) load_chunk(i + 3, s);
        cp_commit();
        s = (s == 2) ? 0 : s + 1;
    }

    // ---- epilogue: bias + relu ----
    const float* be = bias + e * NTOT;
    const int r0 = lane >> 2;
    const int c0 = (lane & 3) * 2;

    if (FUSE_L3) {
        // stage H2 tile (fp32) in smem, then EO = H2 @ Ew3 + Eb3
        constexpr int RS = 132;                 // row stride (floats), +4 pad
        float* H2s = (float*)dsm;               // 128*132*4 = 67584 <= 92160
        __syncthreads();                         // pipeline smem dead now
#pragma unroll
        for (int mi = 0; mi < 2; ++mi)
#pragma unroll
            for (int nt = 0; nt < 8; ++nt) {
                const int col = wn + (nt >> 1) * 16 + (nt & 1) * 8 + c0;
                const float2 bb = *(const float2*)(be + nBase + col);
#pragma unroll
                for (int h = 0; h < 2; ++h) {
                    const int row = wm + mi * 16 + r0 + h * 8;
                    H2s[row * RS + col]     = fmaxf(acc[mi][nt][2 * h + 0] + bb.x, 0.f);
                    H2s[row * RS + col + 1] = fmaxf(acc[mi][nt][2 * h + 1] + bb.y, 0.f);
                }
            }
        __shared__ float Ws[kEH2 * kEO];
        __shared__ float bs[kEO];
        for (int i = tid; i < kEH2 * kEO; i += 256)
            Ws[i] = Ew3[(size_t)e * kEH2 * kEO + i];
        if (tid < kEO) bs[tid] = Eb3[e * kEO + tid];
        __syncthreads();

        // warp w handles rows w*16 .. w*16+15
        for (int r = w * 16; r < w * 16 + 16; ++r) {
            float4 hv = *(const float4*)&H2s[r * RS + lane * 4];
            float o[kEO];
#pragma unroll
            for (int j = 0; j < kEO; ++j) {
                o[j] = hv.x * Ws[(lane * 4 + 0) * kEO + j]
                     + hv.y * Ws[(lane * 4 + 1) * kEO + j]
                     + hv.z * Ws[(lane * 4 + 2) * kEO + j]
                     + hv.w * Ws[(lane * 4 + 3) * kEO + j];
            }
#pragma unroll
            for (int j = 0; j < kEO; ++j)
#pragma unroll
                for (int off = 16; off; off >>= 1)
                    o[j] += __shfl_xor_sync(0xffffffffu, o[j], off);
#pragma unroll
            for (int j = 0; j < kEO; ++j)
                if (lane == j)
                    g_EO[((size_t)e * kB + mBase + r) * kEO + j] = o[j] + bs[j];
        }
    } else {
#pragma unroll
        for (int mi = 0; mi < 2; ++mi)
#pragma unroll
            for (int nt = 0; nt < 8; ++nt) {
                const int col = nBase + wn + (nt >> 1) * 16 + (nt & 1) * 8 + c0;
                const float2 bb = *(const float2*)(be + col);
#pragma unroll
                for (int h = 0; h < 2; ++h) {
                    const int row = mBase + wm + mi * 16 + r0 + h * 8;
                    float v0 = fmaxf(acc[mi][nt][2 * h + 0] + bb.x, 0.f);
                    float v1 = fmaxf(acc[mi][nt][2 * h + 1] + bb.y, 0.f);
                    const size_t off = ((size_t)e * kB + row) * NTOT + col;
                    if (SPLIT_OUT) {
                        __half h0 = __float2half(v0);
                        __half h1 = __float2half(v1);
                        __half2 hv; hv.x = h0; hv.y = h1;
                        __half2 lv;
                        lv.x = __float2half(v0 - __half2float(h0));
                        lv.y = __float2half(v1 - __half2float(h1));
                        *(__half2*)(Chi + off) = hv;
                        *(__half2*)(Clo + off) = lv;
                    }
                }
            }
    }
}

// =====================================================================
// Domain bucketing (order within bucket nondeterministic; per-sample
// results are order-independent so outputs are deterministic).
// =====================================================================
__global__ void bucket_zero() {
    if (threadIdx.x < kD) { g_cnt[threadIdx.x] = 0; g_cur[threadIdx.x] = 0; }
}
__global__ __launch_bounds__(256)
void bucket_count(const int* __restrict__ dom) {
    int i = blockIdx.x * 256 + threadIdx.x;
    atomicAdd(&g_cnt[dom[i]], 1);
}
__global__ void bucket_scan() {
    if (threadIdx.x == 0) {
        int a = 0;
        for (int d = 0; d < kD; ++d) { g_off[d] = a; a += g_cnt[d]; }
    }
}
__global__ __launch_bounds__(256)
void bucket_scatter(const int* __restrict__ dom) {
    int i = blockIdx.x * 256 + threadIdx.x;
    int d = dom[i];
    int p = atomicAdd(&g_cur[d], 1);
    g_order[g_off[d] + p] = i;
}

// =====================================================================
// Bucketed gate + MMoE + tower. Each block serves up to 64 samples of
// ONE domain; Gw1[d] K-chunks staged through smem (reuse x64).
// =====================================================================
constexpr int NS  = 64;   // samples per block-chunk
constexpr int GCH = 16;   // grid.x stride over chunks

__global__ __launch_bounds__(256)
void gate_tower_bucketed(const float* __restrict__ x,
                         const float* __restrict__ Gw1, const float* __restrict__ Gb1,
                         const float* __restrict__ Gw2, const float* __restrict__ Gb2,
                         const float* __restrict__ Tw1, const float* __restrict__ Tb1,
                         const float* __restrict__ Tw2, const float* __restrict__ Tb2,
                         float* __restrict__ out)
{
    __shared__ int   sid[NS];
    __shared__ float Ws[64 * 64];    // Gw1 chunk [k 64][n 64]
    __shared__ float Xs[NS * 64];    // x chunk; reused for gate hidden

    const int d    = blockIdx.y;
    const int cnt  = g_cnt[d];
    const int off  = g_off[d];
    const int tid  = threadIdx.x;
    const int w    = tid >> 5;
    const int lane = tid & 31;
    const int n0   = 2 * lane;

    for (int chunk = blockIdx.x; chunk * NS < cnt; chunk += GCH) {
        const int base = off + chunk * NS;
        const int ns   = min(NS, cnt - chunk * NS);
        if (tid < NS) sid[tid] = (tid < ns) ? g_order[base + tid] : -1;
        __syncthreads();

        float acc[8][2];
#pragma unroll
        for (int s8 = 0; s8 < 8; ++s8) { acc[s8][0] = 0.f; acc[s8][1] = 0.f; }

        const float* W1 = Gw1 + (size_t)d * kIN * kGH;
        for (int k0 = 0; k0 < kIN; k0 += 64) {
            for (int i = tid; i < 64 * 16; i += 256) {
                int r = i >> 4, c4 = (i & 15) * 4;
                *(float4*)&Ws[r * 64 + c4] = *(const float4*)(W1 + (size_t)(k0 + r) * kGH + c4);
            }
            for (int i = tid; i < NS * 16; i += 256) {
                int slot = i >> 4, c4 = (i & 15) * 4;
                int s = sid[slot];
                float4 v = (s >= 0) ? *(const float4*)(x + (size_t)s * kIN + k0 + c4)
                                    : make_float4(0.f, 0.f, 0.f, 0.f);
                *(float4*)&Xs[slot * 64 + c4] = v;
            }
            __syncthreads();
#pragma unroll 4
            for (int kk = 0; kk < 64; ++kk) {
                float2 wv = *(const float2*)&Ws[kk * 64 + n0];
#pragma unroll
                for (int s8 = 0; s8 < 8; ++s8) {
                    float xv = Xs[(w * 8 + s8) * 64 + kk];
                    acc[s8][0] = fmaf(xv, wv.x, acc[s8][0]);
                    acc[s8][1] = fmaf(xv, wv.y, acc[s8][1]);
                }
            }
            __syncthreads();
        }

        float2 gb = *(const float2*)(Gb1 + d * kGH + n0);
#pragma unroll
        for (int s8 = 0; s8 < 8; ++s8) {
            int slot = w * 8 + s8;
            Xs[slot * 64 + n0]     = fmaxf(acc[s8][0] + gb.x, 0.f);
            Xs[slot * 64 + n0 + 1] = fmaxf(acc[s8][1] + gb.y, 0.f);
        }
        __syncthreads();

        for (int slot = w; slot < NS; slot += 8) {
            const int b = sid[slot];
            if (b < 0) continue;
            float g0 = Xs[slot * 64 + lane];
            float g1 = Xs[slot * 64 + lane + 32];

            float logit[kE];
#pragma unroll
            for (int e = 0; e < kE; ++e)
                logit[e] = g0 * Gw2[((size_t)d * kGH + lane) * kE + e]
                         + g1 * Gw2[((size_t)d * kGH + lane + 32) * kE + e];
#pragma unroll
            for (int e = 0; e < kE; ++e)
#pragma unroll
                for (int o = 16; o; o >>= 1)
                    logit[e] += __shfl_xor_sync(0xffffffffu, logit[e], o);

            float mx = -1e30f;
#pragma unroll
            for (int e = 0; e < kE; ++e) {
                logit[e] += Gb2[d * kE + e];
                mx = fmaxf(mx, logit[e]);
            }
            float se = 0.f, gw[kE];
#pragma unroll
            for (int e = 0; e < kE; ++e) { gw[e] = expf(logit[e] - mx); se += gw[e]; }
            float inv = 1.f / se;

            float mmoe = 0.f;
            if (lane < kEO) {
                float avg = 0.f;
#pragma unroll
                for (int e = 0; e < kE; ++e) {
                    float v = g_EO[((size_t)e * kB + b) * kEO + lane];
                    avg += v;
                    mmoe = fmaf(gw[e] * inv, v, mmoe);
                }
                out[kB + (size_t)b * kEO + lane] = avg * (1.f / 6.f);
                out[kB + (size_t)kB * kEO + (size_t)b * kEO + lane] = mmoe;
            }

            float mm[kEO];
#pragma unroll
            for (int o = 0; o < kEO; ++o)
                mm[o] = __shfl_sync(0xffffffffu, mmoe, o);

            float th0 = Tb1[d * 64 + lane];
            float th1 = Tb1[d * 64 + lane + 32];
#pragma unroll
            for (int o = 0; o < kEO; ++o) {
                th0 = fmaf(mm[o], Tw1[((size_t)d * kEO + o) * 64 + lane],      th0);
                th1 = fmaf(mm[o], Tw1[((size_t)d * kEO + o) * 64 + lane + 32], th1);
            }
            th0 = fmaxf(th0, 0.f);
            th1 = fmaxf(th1, 0.f);

            float s = th0 * Tw2[d * 64 + lane] + th1 * Tw2[d * 64 + lane + 32];
#pragma unroll
            for (int o = 16; o; o >>= 1)
                s += __shfl_xor_sync(0xffffffffu, s, o);

            if (lane == 0) {
                float z = s + Tb2[d];
                out[b] = 1.f / (1.f + expf(-z));
            }
        }
        __syncthreads();
    }
}

// =====================================================================
// launch
// =====================================================================
extern "C" void kernel_launch(void* const* d_in, const int* in_sizes, int n_in,
                              void* d_out, int out_size)
{
    const float* x   = (const float*)d_in[0];
    const int*   dom = (const int*)  d_in[1];
    const float* Ew1 = (const float*)d_in[2];
    const float* Eb1 = (const float*)d_in[3];
    const float* Ew2 = (const float*)d_in[4];
    const float* Eb2 = (const float*)d_in[5];
    const float* Ew3 = (const float*)d_in[6];
    const float* Eb3 = (const float*)d_in[7];
    const float* Gw1 = (const float*)d_in[8];
    const float* Gb1 = (const float*)d_in[9];
    const float* Gw2 = (const float*)d_in[10];
    const float* Gb2 = (const float*)d_in[11];
    const float* Tw1 = (const float*)d_in[12];
    const float* Tb1 = (const float*)d_in[13];
    const float* Tw2 = (const float*)d_in[14];
    const float* Tb2 = (const float*)d_in[15];
    float* out = (float*)d_out;

    __half *Xhi, *Xlo, *W1h, *W2h, *H1hi, *H1lo;
    cudaGetSymbolAddress((void**)&Xhi,  g_Xhi);
    cudaGetSymbolAddress((void**)&Xlo,  g_Xlo);
    cudaGetSymbolAddress((void**)&W1h,  g_W1h);
    cudaGetSymbolAddress((void**)&W2h,  g_W2h);
    cudaGetSymbolAddress((void**)&H1hi, g_H1hi);
    cudaGetSymbolAddress((void**)&H1lo, g_H1lo);

    constexpr int SMEM = 3 * 3 * 128 * 80;   // 92160: 3 stages x 3 tiles x 128 x 80B
    cudaFuncSetAttribute(mma_gemm<kEH1, kIN, true, false>,
                         cudaFuncAttributeMaxDynamicSharedMemorySize, SMEM);
    cudaFuncSetAttribute(mma_gemm<kEH2, kEH1, false, true>,
                         cudaFuncAttributeMaxDynamicSharedMemorySize, SMEM);

    // --- bucketing (independent of expert path) ---
    bucket_zero<<<1, 32>>>();
    bucket_count<<<kB / 256, 256>>>(dom);
    bucket_scan<<<1, 32>>>();
    bucket_scatter<<<kB / 256, 256>>>(dom);

    // --- prep: split x (fp16 hi/lo), transpose W1/W2 to fp16 ---
    split_x_kernel<<<(kB * kIN / 4) / 256, 256>>>(
        (const float4*)x, (__half2*)Xhi, (__half2*)Xlo);
    transpose_h_kernel<<<dim3(kIN / 32, kEH1 / 32, kE), dim3(32, 8)>>>(
        Ew1, W1h, kIN, kEH1);
    transpose_h_kernel<<<dim3(kEH1 / 32, kEH2 / 32, kE), dim3(32, 8)>>>(
        Ew2, W2h, kEH1, kEH2);

    // --- expert L1 (HMMA fp16 x2 terms): H1 = relu(x @ Ew1 + b), fp16 hi/lo out ---
    mma_gemm<kEH1, kIN, true, false><<<dim3(kEH1 / 128, kB / 128, kE), 256, SMEM>>>(
        Xhi, Xlo, W1h, Eb1, /*aStride=*/0,
        H1hi, H1lo, nullptr, nullptr);

    // --- expert L2+L3 fused: H2 = relu(H1 @ Ew2 + b); EO = H2 @ Ew3 + b3 ---
    mma_gemm<kEH2, kEH1, false, true><<<dim3(1, kB / 128, kE), 256, SMEM>>>(
        H1hi, H1lo, W2h, Eb2, /*aStride=*/(size_t)kB * kEH1,
        nullptr, nullptr, Ew3, Eb3);

    // --- bucketed gate + MMoE + tower + outputs ---
    gate_tower_bucketed<<<dim3(GCH, kD), 256>>>(x, Gw1, Gb1, Gw2, Gb2,
                                                Tw1, Tb1, Tw2, Tb2, out);
}

// round 14
// speedup vs baseline: 3.2293x; 1.3132x over previous
#include <cuda_runtime.h>
#include <cuda_fp16.h>
#include <math.h>
#include <stdint.h>

// ---------------- problem constants ----------------
constexpr int kB   = 16384;
constexpr int kIN  = 1024;
constexpr int kE   = 6;
constexpr int kD   = 20;
constexpr int kEH1 = 256;
constexpr int kEH2 = 128;
constexpr int kEO  = 10;
constexpr int kGH  = 64;

// ---------------- scratch (device globals: no allocs allowed) ----------------
__device__ __half g_Xh[(size_t)kB * kIN];                  // fp16 x
__device__ __half g_W1h[(size_t)kE * kEH1 * kIN];          // [E][N=256][K=1024] fp16 (transposed)
__device__ __half g_W2h[(size_t)kE * kEH2 * kEH1];         // [E][N=128][K=256]  fp16
__device__ __half g_H1h[(size_t)kE * kB * kEH1];           // relu(L1) fp16
__device__ float  g_EO[(size_t)kE * kB * kEO];             // expert outputs

// domain bucketing scratch
__device__ int g_cnt[kD];
__device__ int g_off[kD];
__device__ int g_order[kB];

// =====================================================================
// PTX helpers (sm_80-era ISA — harness targets plain sm_103, no tcgen05)
// =====================================================================
__device__ __forceinline__ uint32_t smem_u32(const void* p) {
    return (uint32_t)__cvta_generic_to_shared(p);
}
__device__ __forceinline__ void cp_async16(uint32_t dst, const void* src) {
    asm volatile("cp.async.cg.shared.global [%0], [%1], 16;" :: "r"(dst), "l"(src));
}
__device__ __forceinline__ void cp_commit() { asm volatile("cp.async.commit_group;" ::: "memory"); }
__device__ __forceinline__ void cp_wait2()  { asm volatile("cp.async.wait_group 2;" ::: "memory"); }

__device__ __forceinline__ void ldsm4(uint32_t& r0, uint32_t& r1, uint32_t& r2, uint32_t& r3,
                                      uint32_t addr) {
    asm volatile("ldmatrix.sync.aligned.m8n8.x4.shared.b16 {%0,%1,%2,%3}, [%4];"
                 : "=r"(r0), "=r"(r1), "=r"(r2), "=r"(r3) : "r"(addr));
}
__device__ __forceinline__ void mma16816(float* c, const uint32_t* a, uint32_t b0, uint32_t b1) {
    asm volatile("mma.sync.aligned.m16n8k16.row.col.f32.f16.f16.f32 "
                 "{%0,%1,%2,%3},{%4,%5,%6,%7},{%8,%9},{%0,%1,%2,%3};"
                 : "+f"(c[0]), "+f"(c[1]), "+f"(c[2]), "+f"(c[3])
                 : "r"(a[0]), "r"(a[1]), "r"(a[2]), "r"(a[3]), "r"(b0), "r"(b1));
}

// =====================================================================
// Prep: x fp32 -> fp16 (8 elems/thread, 16B stores)
// =====================================================================
__global__ __launch_bounds__(256)
void cvt_x_kernel(const float4* __restrict__ x, uint4* __restrict__ out)
{
    size_t i = (size_t)blockIdx.x * 256 + threadIdx.x;
    float4 a = x[2 * i], b = x[2 * i + 1];
    __half2 h0 = __float22half2_rn(make_float2(a.x, a.y));
    __half2 h1 = __float22half2_rn(make_float2(a.z, a.w));
    __half2 h2 = __float22half2_rn(make_float2(b.x, b.y));
    __half2 h3 = __float22half2_rn(make_float2(b.z, b.w));
    uint4 o;
    o.x = *(uint32_t*)&h0; o.y = *(uint32_t*)&h1;
    o.z = *(uint32_t*)&h2; o.w = *(uint32_t*)&h3;
    out[i] = o;
}

// =====================================================================
// Prep: W [E][K][N] fp32 -> W^T fp16 [E][N][K]
// =====================================================================
__global__ __launch_bounds__(256)
void transpose_h_kernel(const float* __restrict__ W, __half* __restrict__ hi,
                        int K, int N)
{
    __shared__ float t[32][33];
    const int e = blockIdx.z;
    const float* We = W + (size_t)e * K * N;
    const int k0 = blockIdx.x * 32, n0 = blockIdx.y * 32;
    const int tx = threadIdx.x, ty = threadIdx.y;
    for (int i = ty; i < 32; i += 8)
        t[i][tx] = We[(size_t)(k0 + i) * N + n0 + tx];
    __syncthreads();
    for (int i = ty; i < 32; i += 8) {
        size_t o = ((size_t)e * N + n0 + i) * K + k0 + tx;
        hi[o] = __float2half(t[tx][i]);   // = W[k0+tx][n0+i]
    }
}

// =====================================================================
// mma.sync fp16 GEMM (single term, fp32 accumulate):
//   C[e][M,NTOT] = relu( A[e][M,KTOT] @ W[e][NTOT,KTOT]^T + bias[e] )
// CTA 128x128, BK=64, 3-stage cp.async, 8 warps (4m x 2n), warp 32x64.
// ROWB=144: 128B data + 16B pad; 36-word stride is a perfect 8-row bank
// permutation -> conflict-free ldmatrix.
// HALF_OUT: emit fp16 (feeds next layer).
// FUSE_L3:  stage H2 in smem, compute EO = H2 @ Ew3 + Eb3 in-kernel.
// =====================================================================
template<int NTOT, int KTOT, bool HALF_OUT, bool FUSE_L3>
__global__ __launch_bounds__(256, 2)
void mma_gemm(const __half* __restrict__ Ahb, const __half* __restrict__ Wh_all,
              const float* __restrict__ bias, size_t aStride,
              __half* __restrict__ Chi,
              const float* __restrict__ Ew3, const float* __restrict__ Eb3)
{
    constexpr int BK = 64;
    constexpr int NCHUNK = KTOT / BK;
    constexpr int ROWB = 144;                // 128B data + 16B pad
    constexpr int T_SZ = 128 * ROWB;         // 18432 per tile
    constexpr int STAGE = 2 * T_SZ;          // A + W = 36864
    // dynamic smem = 3 stages = 110592; 2 CTAs/SM = 221184 <= 228KB

    extern __shared__ char dsm[];
    const uint32_t sb = smem_u32(dsm);

    const int tid  = threadIdx.x;
    const int w    = tid >> 5;
    const int lane = tid & 31;
    const int e     = blockIdx.z;
    const int mBase = blockIdx.y * 128;
    const int nBase = blockIdx.x * 128;
    const int wm = (w & 3) * 32;
    const int wn = (w >> 2) * 64;

    const __half* Ah = Ahb + (size_t)e * aStride;
    const __half* Wh = Wh_all + (size_t)e * NTOT * KTOT;

    auto load_chunk = [&](int c, int s) {
        const uint32_t st = sb + s * STAGE;
        // seg 0: A, seg 1: W ; each 128 rows x 8 granules of 16B (BK=64)
#pragma unroll
        for (int g = tid; g < 2048; g += 256) {
            const int seg = g >> 10;
            const int idx = g & 1023;
            const int row = idx >> 3, gr = idx & 7;
            const __half* base = seg ? Wh : Ah;
            const size_t grow = seg ? (size_t)(nBase + row) : (size_t)(mBase + row);
            cp_async16(st + seg * T_SZ + row * ROWB + gr * 16,
                       base + grow * KTOT + c * BK + gr * 8);
        }
    };

    float acc[2][8][4];
#pragma unroll
    for (int i = 0; i < 2; ++i)
#pragma unroll
        for (int j = 0; j < 8; ++j)
#pragma unroll
            for (int q = 0; q < 4; ++q) acc[i][j][q] = 0.f;

    load_chunk(0, 0); cp_commit();
    if (NCHUNK > 1) load_chunk(1, 1); cp_commit();
    if (NCHUNK > 2) load_chunk(2, 2); cp_commit();

    const int lr = lane & 15;
    const int lc = (lane >> 4) * 16;   // byte offset of 8-col half

    int s = 0;
    for (int i = 0; i < NCHUNK; ++i) {
        cp_wait2();
        __syncthreads();
        const uint32_t st    = sb + s * STAGE;
        const uint32_t aBase = st + wm * ROWB;
        const uint32_t bBase = st + T_SZ + wn * ROWB;

#pragma unroll
        for (int ks = 0; ks < 4; ++ks) {
            const uint32_t koff = ks * 32 + lc;
            uint32_t ah[2][4], bh[4][4];
#pragma unroll
            for (int mi = 0; mi < 2; ++mi)
                ldsm4(ah[mi][0], ah[mi][1], ah[mi][2], ah[mi][3],
                      aBase + (mi * 16 + lr) * ROWB + koff);
#pragma unroll
            for (int nj = 0; nj < 4; ++nj)
                ldsm4(bh[nj][0], bh[nj][1], bh[nj][2], bh[nj][3],
                      bBase + (nj * 16 + lr) * ROWB + koff);
#pragma unroll
            for (int mi = 0; mi < 2; ++mi)
#pragma unroll
                for (int nj = 0; nj < 4; ++nj)
#pragma unroll
                    for (int t = 0; t < 2; ++t)
                        mma16816(acc[mi][nj * 2 + t], ah[mi], bh[nj][t], bh[nj][t + 2]);
        }
        __syncthreads();
        if (i + 3 < NCHUNK) load_chunk(i + 3, s);
        cp_commit();
        s = (s == 2) ? 0 : s + 1;
    }

    // ---- epilogue: bias + relu ----
    const float* be = bias + e * NTOT;
    const int r0 = lane >> 2;
    const int c0 = (lane & 3) * 2;

    if (FUSE_L3) {
        // stage H2 tile (fp32) in smem, then EO = H2 @ Ew3 + Eb3
        constexpr int RS = 132;                 // row stride (floats), +4 pad
        float* H2s = (float*)dsm;               // 128*132*4 = 67584 <= 110592
        __syncthreads();                        // pipeline smem dead now
#pragma unroll
        for (int mi = 0; mi < 2; ++mi)
#pragma unroll
            for (int nt = 0; nt < 8; ++nt) {
                const int col = wn + (nt >> 1) * 16 + (nt & 1) * 8 + c0;
                const float2 bb = *(const float2*)(be + nBase + col);
#pragma unroll
                for (int h = 0; h < 2; ++h) {
                    const int row = wm + mi * 16 + r0 + h * 8;
                    H2s[row * RS + col]     = fmaxf(acc[mi][nt][2 * h + 0] + bb.x, 0.f);
                    H2s[row * RS + col + 1] = fmaxf(acc[mi][nt][2 * h + 1] + bb.y, 0.f);
                }
            }
        __shared__ float Ws[kEH2 * kEO];
        __shared__ float bs[kEO];
        for (int i = tid; i < kEH2 * kEO; i += 256)
            Ws[i] = Ew3[(size_t)e * kEH2 * kEO + i];
        if (tid < kEO) bs[tid] = Eb3[e * kEO + tid];
        __syncthreads();

        // warp w handles rows w*16 .. w*16+15
        for (int r = w * 16; r < w * 16 + 16; ++r) {
            float4 hv = *(const float4*)&H2s[r * RS + lane * 4];
            float o[kEO];
#pragma unroll
            for (int j = 0; j < kEO; ++j) {
                o[j] = hv.x * Ws[(lane * 4 + 0) * kEO + j]
                     + hv.y * Ws[(lane * 4 + 1) * kEO + j]
                     + hv.z * Ws[(lane * 4 + 2) * kEO + j]
                     + hv.w * Ws[(lane * 4 + 3) * kEO + j];
            }
#pragma unroll
            for (int j = 0; j < kEO; ++j)
#pragma unroll
                for (int off = 16; off; off >>= 1)
                    o[j] += __shfl_xor_sync(0xffffffffu, o[j], off);
#pragma unroll
            for (int j = 0; j < kEO; ++j)
                if (lane == j)
                    g_EO[((size_t)e * kB + mBase + r) * kEO + j] = o[j] + bs[j];
        }
    } else {
#pragma unroll
        for (int mi = 0; mi < 2; ++mi)
#pragma unroll
            for (int nt = 0; nt < 8; ++nt) {
                const int col = nBase + wn + (nt >> 1) * 16 + (nt & 1) * 8 + c0;
                const float2 bb = *(const float2*)(be + col);
#pragma unroll
                for (int h = 0; h < 2; ++h) {
                    const int row = mBase + wm + mi * 16 + r0 + h * 8;
                    float v0 = fmaxf(acc[mi][nt][2 * h + 0] + bb.x, 0.f);
                    float v1 = fmaxf(acc[mi][nt][2 * h + 1] + bb.y, 0.f);
                    if (HALF_OUT) {
                        const size_t off = ((size_t)e * kB + row) * NTOT + col;
                        __half2 hv = __float22half2_rn(make_float2(v0, v1));
                        *(__half2*)(Chi + off) = hv;
                    }
                }
            }
    }
}

// =====================================================================
// Domain bucketing: single CTA, smem histogram + scan + scatter.
// Order within bucket nondeterministic; per-sample results are
// order-independent so outputs are deterministic.
// =====================================================================
__global__ __launch_bounds__(1024)
void bucket_all(const int* __restrict__ dom)
{
    __shared__ int cnt[kD], cur[kD];
    const int t = threadIdx.x;
    if (t < kD) cnt[t] = 0;
    __syncthreads();
    for (int i = t; i < kB; i += 1024)
        atomicAdd(&cnt[dom[i]], 1);
    __syncthreads();
    if (t == 0) {
        int a = 0;
        for (int d = 0; d < kD; ++d) {
            g_off[d] = a; cur[d] = a; g_cnt[d] = cnt[d];
            a += cnt[d];
        }
    }
    __syncthreads();
    for (int i = t; i < kB; i += 1024) {
        int p = atomicAdd(&cur[dom[i]], 1);
        g_order[p] = i;
    }
}

// =====================================================================
// Bucketed gate + MMoE + tower. Each block serves up to 64 samples of
// ONE domain; Gw1[d] K-chunks staged through smem (reuse x64).
// =====================================================================
constexpr int NS  = 64;   // samples per block-chunk
constexpr int GCH = 16;   // grid.x stride over chunks

__global__ __launch_bounds__(256)
void gate_tower_bucketed(const float* __restrict__ x,
                         const float* __restrict__ Gw1, const float* __restrict__ Gb1,
                         const float* __restrict__ Gw2, const float* __restrict__ Gb2,
                         const float* __restrict__ Tw1, const float* __restrict__ Tb1,
                         const float* __restrict__ Tw2, const float* __restrict__ Tb2,
                         float* __restrict__ out)
{
    __shared__ int   sid[NS];
    __shared__ float Ws[64 * 64];    // Gw1 chunk [k 64][n 64]
    __shared__ float Xs[NS * 64];    // x chunk; reused for gate hidden

    const int d    = blockIdx.y;
    const int cnt  = g_cnt[d];
    const int off  = g_off[d];
    const int tid  = threadIdx.x;
    const int w    = tid >> 5;
    const int lane = tid & 31;
    const int n0   = 2 * lane;

    for (int chunk = blockIdx.x; chunk * NS < cnt; chunk += GCH) {
        const int base = off + chunk * NS;
        const int ns   = min(NS, cnt - chunk * NS);
        if (tid < NS) sid[tid] = (tid < ns) ? g_order[base + tid] : -1;
        __syncthreads();

        float acc[8][2];
#pragma unroll
        for (int s8 = 0; s8 < 8; ++s8) { acc[s8][0] = 0.f; acc[s8][1] = 0.f; }

        const float* W1 = Gw1 + (size_t)d * kIN * kGH;
        for (int k0 = 0; k0 < kIN; k0 += 64) {
            for (int i = tid; i < 64 * 16; i += 256) {
                int r = i >> 4, c4 = (i & 15) * 4;
                *(float4*)&Ws[r * 64 + c4] = *(const float4*)(W1 + (size_t)(k0 + r) * kGH + c4);
            }
            for (int i = tid; i < NS * 16; i += 256) {
                int slot = i >> 4, c4 = (i & 15) * 4;
                int s = sid[slot];
                float4 v = (s >= 0) ? *(const float4*)(x + (size_t)s * kIN + k0 + c4)
                                    : make_float4(0.f, 0.f, 0.f, 0.f);
                *(float4*)&Xs[slot * 64 + c4] = v;
            }
            __syncthreads();
#pragma unroll 4
            for (int kk = 0; kk < 64; ++kk) {
                float2 wv = *(const float2*)&Ws[kk * 64 + n0];
#pragma unroll
                for (int s8 = 0; s8 < 8; ++s8) {
                    float xv = Xs[(w * 8 + s8) * 64 + kk];
                    acc[s8][0] = fmaf(xv, wv.x, acc[s8][0]);
                    acc[s8][1] = fmaf(xv, wv.y, acc[s8][1]);
                }
            }
            __syncthreads();
        }

        float2 gb = *(const float2*)(Gb1 + d * kGH + n0);
#pragma unroll
        for (int s8 = 0; s8 < 8; ++s8) {
            int slot = w * 8 + s8;
            Xs[slot * 64 + n0]     = fmaxf(acc[s8][0] + gb.x, 0.f);
            Xs[slot * 64 + n0 + 1] = fmaxf(acc[s8][1] + gb.y, 0.f);
        }
        __syncthreads();

        for (int slot = w; slot < NS; slot += 8) {
            const int b = sid[slot];
            if (b < 0) continue;
            float g0 = Xs[slot * 64 + lane];
            float g1 = Xs[slot * 64 + lane + 32];

            float logit[kE];
#pragma unroll
            for (int e = 0; e < kE; ++e)
                logit[e] = g0 * Gw2[((size_t)d * kGH + lane) * kE + e]
                         + g1 * Gw2[((size_t)d * kGH + lane + 32) * kE + e];
#pragma unroll
            for (int e = 0; e < kE; ++e)
#pragma unroll
                for (int o = 16; o; o >>= 1)
                    logit[e] += __shfl_xor_sync(0xffffffffu, logit[e], o);

            float mx = -1e30f;
#pragma unroll
            for (int e = 0; e < kE; ++e) {
                logit[e] += Gb2[d * kE + e];
                mx = fmaxf(mx, logit[e]);
            }
            float se = 0.f, gw[kE];
#pragma unroll
            for (int e = 0; e < kE; ++e) { gw[e] = expf(logit[e] - mx); se += gw[e]; }
            float inv = 1.f / se;

            float mmoe = 0.f;
            if (lane < kEO) {
                float avg = 0.f;
#pragma unroll
                for (int e = 0; e < kE; ++e) {
                    float v = g_EO[((size_t)e * kB + b) * kEO + lane];
                    avg += v;
                    mmoe = fmaf(gw[e] * inv, v, mmoe);
                }
                out[kB + (size_t)b * kEO + lane] = avg * (1.f / 6.f);
                out[kB + (size_t)kB * kEO + (size_t)b * kEO + lane] = mmoe;
            }

            float mm[kEO];
#pragma unroll
            for (int o = 0; o < kEO; ++o)
                mm[o] = __shfl_sync(0xffffffffu, mmoe, o);

            float th0 = Tb1[d * 64 + lane];
            float th1 = Tb1[d * 64 + lane + 32];
#pragma unroll
            for (int o = 0; o < kEO; ++o) {
                th0 = fmaf(mm[o], Tw1[((size_t)d * kEO + o) * 64 + lane],      th0);
                th1 = fmaf(mm[o], Tw1[((size_t)d * kEO + o) * 64 + lane + 32], th1);
            }
            th0 = fmaxf(th0, 0.f);
            th1 = fmaxf(th1, 0.f);

            float s = th0 * Tw2[d * 64 + lane] + th1 * Tw2[d * 64 + lane + 32];
#pragma unroll
            for (int o = 16; o; o >>= 1)
                s += __shfl_xor_sync(0xffffffffu, s, o);

            if (lane == 0) {
                float z = s + Tb2[d];
                out[b] = 1.f / (1.f + expf(-z));
            }
        }
        __syncthreads();
    }
}

// =====================================================================
// launch
// =====================================================================
extern "C" void kernel_launch(void* const* d_in, const int* in_sizes, int n_in,
                              void* d_out, int out_size)
{
    const float* x   = (const float*)d_in[0];
    const int*   dom = (const int*)  d_in[1];
    const float* Ew1 = (const float*)d_in[2];
    const float* Eb1 = (const float*)d_in[3];
    const float* Ew2 = (const float*)d_in[4];
    const float* Eb2 = (const float*)d_in[5];
    const float* Ew3 = (const float*)d_in[6];
    const float* Eb3 = (const float*)d_in[7];
    const float* Gw1 = (const float*)d_in[8];
    const float* Gb1 = (const float*)d_in[9];
    const float* Gw2 = (const float*)d_in[10];
    const float* Gb2 = (const float*)d_in[11];
    const float* Tw1 = (const float*)d_in[12];
    const float* Tb1 = (const float*)d_in[13];
    const float* Tw2 = (const float*)d_in[14];
    const float* Tb2 = (const float*)d_in[15];
    float* out = (float*)d_out;

    __half *Xh, *W1h, *W2h, *H1h;
    cudaGetSymbolAddress((void**)&Xh,  g_Xh);
    cudaGetSymbolAddress((void**)&W1h, g_W1h);
    cudaGetSymbolAddress((void**)&W2h, g_W2h);
    cudaGetSymbolAddress((void**)&H1h, g_H1h);

    constexpr int SMEM = 3 * 2 * 128 * 144;   // 110592: 3 stages x (A+W) x 128 x 144B
    cudaFuncSetAttribute(mma_gemm<kEH1, kIN, true, false>,
                         cudaFuncAttributeMaxDynamicSharedMemorySize, SMEM);
    cudaFuncSetAttribute(mma_gemm<kEH2, kEH1, false, true>,
                         cudaFuncAttributeMaxDynamicSharedMemorySize, SMEM);

    // --- bucketing (single kernel) ---
    bucket_all<<<1, 1024>>>(dom);

    // --- prep: x -> fp16, transpose W1/W2 to fp16 ---
    cvt_x_kernel<<<(kB * kIN / 8) / 256, 256>>>((const float4*)x, (uint4*)Xh);
    transpose_h_kernel<<<dim3(kIN / 32, kEH1 / 32, kE), dim3(32, 8)>>>(
        Ew1, W1h, kIN, kEH1);
    transpose_h_kernel<<<dim3(kEH1 / 32, kEH2 / 32, kE), dim3(32, 8)>>>(
        Ew2, W2h, kEH1, kEH2);

    // --- expert L1 (HMMA fp16): H1 = relu(x @ Ew1 + b), fp16 out ---
    mma_gemm<kEH1, kIN, true, false><<<dim3(kEH1 / 128, kB / 128, kE), 256, SMEM>>>(
        Xh, W1h, Eb1, /*aStride=*/0, H1h, nullptr, nullptr);

    // --- expert L2+L3 fused: H2 = relu(H1 @ Ew2 + b); EO = H2 @ Ew3 + b3 ---
    mma_gemm<kEH2, kEH1, false, true><<<dim3(1, kB / 128, kE), 256, SMEM>>>(
        H1h, W2h, Eb2, /*aStride=*/(size_t)kB * kEH1, nullptr, Ew3, Eb3);

    // --- bucketed gate + MMoE + tower + outputs ---
    gate_tower_bucketed<<<dim3(GCH, kD), 256>>>(x, Gw1, Gb1, Gw2, Gb2,
                                                Tw1, Tb1, Tw2, Tb2, out);
}

// round 15
// speedup vs baseline: 4.0002x; 1.2387x over previous
#include <cuda_runtime.h>
#include <cuda_fp16.h>
#include <math.h>
#include <stdint.h>

// ---------------- problem constants ----------------
constexpr int kB   = 16384;
constexpr int kIN  = 1024;
constexpr int kE   = 6;
constexpr int kD   = 20;
constexpr int kEH1 = 256;
constexpr int kEH2 = 128;
constexpr int kEO  = 10;
constexpr int kGH  = 64;

// ---------------- scratch (device globals: no allocs allowed) ----------------
__device__ __half g_Xh[(size_t)kB * kIN];                  // fp16 x
__device__ __half g_W1h[(size_t)kE * kEH1 * kIN];          // [E][N=256][K=1024] fp16 (transposed)
__device__ __half g_W2h[(size_t)kE * kEH2 * kEH1];         // [E][N=128][K=256]  fp16
__device__ __half g_G1h[(size_t)kD * kGH * kIN];           // [D][N=64][K=1024]  fp16 (transposed)
__device__ __half g_H1h[(size_t)kE * kB * kEH1];           // relu(L1) fp16
__device__ float  g_EO[(size_t)kE * kB * kEO];             // expert outputs

// domain bucketing scratch
__device__ int g_cnt[kD];
__device__ int g_off[kD];
__device__ int g_order[kB];

// =====================================================================
// PTX helpers (sm_80-era ISA — harness targets plain sm_103, no tcgen05)
// =====================================================================
__device__ __forceinline__ uint32_t smem_u32(const void* p) {
    return (uint32_t)__cvta_generic_to_shared(p);
}
__device__ __forceinline__ void cp_async16(uint32_t dst, const void* src) {
    asm volatile("cp.async.cg.shared.global [%0], [%1], 16;" :: "r"(dst), "l"(src));
}
__device__ __forceinline__ void cp_commit() { asm volatile("cp.async.commit_group;" ::: "memory"); }
__device__ __forceinline__ void cp_wait2()  { asm volatile("cp.async.wait_group 2;" ::: "memory"); }
__device__ __forceinline__ void cp_wait1()  { asm volatile("cp.async.wait_group 1;" ::: "memory"); }

__device__ __forceinline__ void ldsm4(uint32_t& r0, uint32_t& r1, uint32_t& r2, uint32_t& r3,
                                      uint32_t addr) {
    asm volatile("ldmatrix.sync.aligned.m8n8.x4.shared.b16 {%0,%1,%2,%3}, [%4];"
                 : "=r"(r0), "=r"(r1), "=r"(r2), "=r"(r3) : "r"(addr));
}
__device__ __forceinline__ void mma16816(float* c, const uint32_t* a, uint32_t b0, uint32_t b1) {
    asm volatile("mma.sync.aligned.m16n8k16.row.col.f32.f16.f16.f32 "
                 "{%0,%1,%2,%3},{%4,%5,%6,%7},{%8,%9},{%0,%1,%2,%3};"
                 : "+f"(c[0]), "+f"(c[1]), "+f"(c[2]), "+f"(c[3])
                 : "r"(a[0]), "r"(a[1]), "r"(a[2]), "r"(a[3]), "r"(b0), "r"(b1));
}

// =====================================================================
// Prep: x fp32 -> fp16 (8 elems/thread, 16B stores)
// =====================================================================
__global__ __launch_bounds__(256)
void cvt_x_kernel(const float4* __restrict__ x, uint4* __restrict__ out)
{
    size_t i = (size_t)blockIdx.x * 256 + threadIdx.x;
    float4 a = x[2 * i], b = x[2 * i + 1];
    __half2 h0 = __float22half2_rn(make_float2(a.x, a.y));
    __half2 h1 = __float22half2_rn(make_float2(a.z, a.w));
    __half2 h2 = __float22half2_rn(make_float2(b.x, b.y));
    __half2 h3 = __float22half2_rn(make_float2(b.z, b.w));
    uint4 o;
    o.x = *(uint32_t*)&h0; o.y = *(uint32_t*)&h1;
    o.z = *(uint32_t*)&h2; o.w = *(uint32_t*)&h3;
    out[i] = o;
}

// =====================================================================
// Prep: W [Z][K][N] fp32 -> W^T fp16 [Z][N][K]
// =====================================================================
__global__ __launch_bounds__(256)
void transpose_h_kernel(const float* __restrict__ W, __half* __restrict__ hi,
                        int K, int N)
{
    __shared__ float t[32][33];
    const int e = blockIdx.z;
    const float* We = W + (size_t)e * K * N;
    const int k0 = blockIdx.x * 32, n0 = blockIdx.y * 32;
    const int tx = threadIdx.x, ty = threadIdx.y;
    for (int i = ty; i < 32; i += 8)
        t[i][tx] = We[(size_t)(k0 + i) * N + n0 + tx];
    __syncthreads();
    for (int i = ty; i < 32; i += 8) {
        size_t o = ((size_t)e * N + n0 + i) * K + k0 + tx;
        hi[o] = __float2half(t[tx][i]);   // = W[k0+tx][n0+i]
    }
}

// =====================================================================
// mma.sync fp16 GEMM (single term, fp32 accumulate):
//   C[e][M,NTOT] = relu( A[e][M,KTOT] @ W[e][NTOT,KTOT]^T + bias[e] )
// CTA 128x128, BK=64, 3-stage cp.async, 8 warps (4m x 2n), warp 32x64.
// =====================================================================
template<int NTOT, int KTOT, bool HALF_OUT, bool FUSE_L3>
__global__ __launch_bounds__(256, 2)
void mma_gemm(const __half* __restrict__ Ahb, const __half* __restrict__ Wh_all,
              const float* __restrict__ bias, size_t aStride,
              __half* __restrict__ Chi,
              const float* __restrict__ Ew3, const float* __restrict__ Eb3)
{
    constexpr int BK = 64;
    constexpr int NCHUNK = KTOT / BK;
    constexpr int ROWB = 144;                // 128B data + 16B pad
    constexpr int T_SZ = 128 * ROWB;         // 18432 per tile
    constexpr int STAGE = 2 * T_SZ;          // A + W = 36864

    extern __shared__ char dsm[];
    const uint32_t sb = smem_u32(dsm);

    const int tid  = threadIdx.x;
    const int w    = tid >> 5;
    const int lane = tid & 31;
    const int e     = blockIdx.z;
    const int mBase = blockIdx.y * 128;
    const int nBase = blockIdx.x * 128;
    const int wm = (w & 3) * 32;
    const int wn = (w >> 2) * 64;

    const __half* Ah = Ahb + (size_t)e * aStride;
    const __half* Wh = Wh_all + (size_t)e * NTOT * KTOT;

    auto load_chunk = [&](int c, int s) {
        const uint32_t st = sb + s * STAGE;
#pragma unroll
        for (int g = tid; g < 2048; g += 256) {
            const int seg = g >> 10;
            const int idx = g & 1023;
            const int row = idx >> 3, gr = idx & 7;
            const __half* base = seg ? Wh : Ah;
            const size_t grow = seg ? (size_t)(nBase + row) : (size_t)(mBase + row);
            cp_async16(st + seg * T_SZ + row * ROWB + gr * 16,
                       base + grow * KTOT + c * BK + gr * 8);
        }
    };

    float acc[2][8][4];
#pragma unroll
    for (int i = 0; i < 2; ++i)
#pragma unroll
        for (int j = 0; j < 8; ++j)
#pragma unroll
            for (int q = 0; q < 4; ++q) acc[i][j][q] = 0.f;

    load_chunk(0, 0); cp_commit();
    if (NCHUNK > 1) load_chunk(1, 1); cp_commit();
    if (NCHUNK > 2) load_chunk(2, 2); cp_commit();

    const int lr = lane & 15;
    const int lc = (lane >> 4) * 16;

    int s = 0;
    for (int i = 0; i < NCHUNK; ++i) {
        cp_wait2();
        __syncthreads();
        const uint32_t st    = sb + s * STAGE;
        const uint32_t aBase = st + wm * ROWB;
        const uint32_t bBase = st + T_SZ + wn * ROWB;

#pragma unroll
        for (int ks = 0; ks < 4; ++ks) {
            const uint32_t koff = ks * 32 + lc;
            uint32_t ah[2][4], bh[4][4];
#pragma unroll
            for (int mi = 0; mi < 2; ++mi)
                ldsm4(ah[mi][0], ah[mi][1], ah[mi][2], ah[mi][3],
                      aBase + (mi * 16 + lr) * ROWB + koff);
#pragma unroll
            for (int nj = 0; nj < 4; ++nj)
                ldsm4(bh[nj][0], bh[nj][1], bh[nj][2], bh[nj][3],
                      bBase + (nj * 16 + lr) * ROWB + koff);
#pragma unroll
            for (int mi = 0; mi < 2; ++mi)
#pragma unroll
                for (int nj = 0; nj < 4; ++nj)
#pragma unroll
                    for (int t = 0; t < 2; ++t)
                        mma16816(acc[mi][nj * 2 + t], ah[mi], bh[nj][t], bh[nj][t + 2]);
        }
        __syncthreads();
        if (i + 3 < NCHUNK) load_chunk(i + 3, s);
        cp_commit();
        s = (s == 2) ? 0 : s + 1;
    }

    // ---- epilogue: bias + relu ----
    const float* be = bias + e * NTOT;
    const int r0 = lane >> 2;
    const int c0 = (lane & 3) * 2;

    if (FUSE_L3) {
        constexpr int RS = 132;
        float* H2s = (float*)dsm;
        __syncthreads();
#pragma unroll
        for (int mi = 0; mi < 2; ++mi)
#pragma unroll
            for (int nt = 0; nt < 8; ++nt) {
                const int col = wn + (nt >> 1) * 16 + (nt & 1) * 8 + c0;
                const float2 bb = *(const float2*)(be + nBase + col);
#pragma unroll
                for (int h = 0; h < 2; ++h) {
                    const int row = wm + mi * 16 + r0 + h * 8;
                    H2s[row * RS + col]     = fmaxf(acc[mi][nt][2 * h + 0] + bb.x, 0.f);
                    H2s[row * RS + col + 1] = fmaxf(acc[mi][nt][2 * h + 1] + bb.y, 0.f);
                }
            }
        __shared__ float Ws[kEH2 * kEO];
        __shared__ float bs[kEO];
        for (int i = tid; i < kEH2 * kEO; i += 256)
            Ws[i] = Ew3[(size_t)e * kEH2 * kEO + i];
        if (tid < kEO) bs[tid] = Eb3[e * kEO + tid];
        __syncthreads();

        for (int r = w * 16; r < w * 16 + 16; ++r) {
            float4 hv = *(const float4*)&H2s[r * RS + lane * 4];
            float o[kEO];
#pragma unroll
            for (int j = 0; j < kEO; ++j) {
                o[j] = hv.x * Ws[(lane * 4 + 0) * kEO + j]
                     + hv.y * Ws[(lane * 4 + 1) * kEO + j]
                     + hv.z * Ws[(lane * 4 + 2) * kEO + j]
                     + hv.w * Ws[(lane * 4 + 3) * kEO + j];
            }
#pragma unroll
            for (int j = 0; j < kEO; ++j)
#pragma unroll
                for (int off = 16; off; off >>= 1)
                    o[j] += __shfl_xor_sync(0xffffffffu, o[j], off);
#pragma unroll
            for (int j = 0; j < kEO; ++j)
                if (lane == j)
                    g_EO[((size_t)e * kB + mBase + r) * kEO + j] = o[j] + bs[j];
        }
    } else {
#pragma unroll
        for (int mi = 0; mi < 2; ++mi)
#pragma unroll
            for (int nt = 0; nt < 8; ++nt) {
                const int col = nBase + wn + (nt >> 1) * 16 + (nt & 1) * 8 + c0;
                const float2 bb = *(const float2*)(be + col);
#pragma unroll
                for (int h = 0; h < 2; ++h) {
                    const int row = mBase + wm + mi * 16 + r0 + h * 8;
                    float v0 = fmaxf(acc[mi][nt][2 * h + 0] + bb.x, 0.f);
                    float v1 = fmaxf(acc[mi][nt][2 * h + 1] + bb.y, 0.f);
                    if (HALF_OUT) {
                        const size_t off = ((size_t)e * kB + row) * NTOT + col;
                        __half2 hv = __float22half2_rn(make_float2(v0, v1));
                        *(__half2*)(Chi + off) = hv;
                    }
                }
            }
    }
}

// =====================================================================
// Domain bucketing: single CTA, smem histogram + scan + scatter.
// =====================================================================
__global__ __launch_bounds__(1024)
void bucket_all(const int* __restrict__ dom)
{
    __shared__ int cnt[kD], cur[kD];
    const int t = threadIdx.x;
    if (t < kD) cnt[t] = 0;
    __syncthreads();
    for (int i = t; i < kB; i += 1024)
        atomicAdd(&cnt[dom[i]], 1);
    __syncthreads();
    if (t == 0) {
        int a = 0;
        for (int d = 0; d < kD; ++d) {
            g_off[d] = a; cur[d] = a; g_cnt[d] = cnt[d];
            a += cnt[d];
        }
    }
    __syncthreads();
    for (int i = t; i < kB; i += 1024) {
        int p = atomicAdd(&cur[dom[i]], 1);
        g_order[p] = i;
    }
}

// =====================================================================
// Bucketed gate (HMMA) + MMoE + tower. Each block-chunk = 64 samples of
// ONE domain. Hidden layer: gathered-x fp16 @ Gw1^T fp16 via mma.sync,
// 2-stage cp.async, BK=128, warp tile 16x32 (8 warps = 64x64).
// Then per-sample softmax/MMoE/tower tail (fp32).
// =====================================================================
constexpr int NS  = 64;   // samples per block-chunk
constexpr int GCH = 16;   // grid.x stride over chunks

__global__ __launch_bounds__(256)
void gate_tower_bucketed(const float* __restrict__ x,
                         const float* __restrict__ Gb1,
                         const float* __restrict__ Gw2, const float* __restrict__ Gb2,
                         const float* __restrict__ Tw1, const float* __restrict__ Tb1,
                         const float* __restrict__ Tw2, const float* __restrict__ Tb2,
                         float* __restrict__ out)
{
    constexpr int BK   = 128;
    constexpr int ROWB = 272;               // 256B data + 16B pad (stride%32w = 4 -> conflict-free)
    constexpr int T_SZ = NS * ROWB;         // 17408
    constexpr int STAGE = 2 * T_SZ;         // A + W = 34816
    constexpr int NCHUNK = kIN / BK;        // 8

    extern __shared__ char dsm[];           // 2 stages = 69632
    const uint32_t sb = smem_u32(dsm);
    float* Hs = (float*)dsm;                // hidden [64][64] fp32, reused after GEMM

    __shared__ int sid[NS];

    const int d    = blockIdx.y;
    const int cnt  = g_cnt[d];
    const int off  = g_off[d];
    const int tid  = threadIdx.x;
    const int w    = tid >> 5;
    const int lane = tid & 31;

    const __half* Wd = g_G1h + (size_t)d * kGH * kIN;

    const int wm = (w & 3) * 16;            // warp row base (16 rows)
    const int wn = (w >> 2) * 32;           // warp col base (32 cols)
    const int lr = lane & 15;
    const int lc = (lane >> 4) * 16;
    const int r0 = lane >> 2;
    const int c0 = (lane & 3) * 2;

    for (int chunk = blockIdx.x; chunk * NS < cnt; chunk += GCH) {
        const int base = off + chunk * NS;
        const int ns   = min(NS, cnt - chunk * NS);
        if (tid < NS) sid[tid] = (tid < ns) ? g_order[base + tid] : -1;
        __syncthreads();

        auto load_chunk = [&](int c, int s) {
            const uint32_t st = sb + s * STAGE;
            // A: 64 rows x 16 granules ; W: 64 rows x 16 granules
#pragma unroll
            for (int g = tid; g < 2048; g += 256) {
                const int seg = g >> 10;
                const int idx = g & 1023;
                const int row = idx >> 4, gr = idx & 15;
                const __half* src;
                if (seg == 0) {
                    int sr = sid[row];
                    src = g_Xh + (size_t)(sr < 0 ? 0 : sr) * kIN + c * BK + gr * 8;
                } else {
                    src = Wd + (size_t)row * kIN + c * BK + gr * 8;
                }
                cp_async16(st + seg * T_SZ + row * ROWB + gr * 16, src);
            }
        };

        float acc[4][4];
#pragma unroll
        for (int j = 0; j < 4; ++j)
#pragma unroll
            for (int q = 0; q < 4; ++q) acc[j][q] = 0.f;

        load_chunk(0, 0); cp_commit();
        load_chunk(1, 1); cp_commit();

        for (int i = 0; i < NCHUNK; ++i) {
            const int s = i & 1;
            cp_wait1();
            __syncthreads();
            const uint32_t st    = sb + s * STAGE;
            const uint32_t aBase = st + wm * ROWB;
            const uint32_t bBase = st + T_SZ + wn * ROWB;

#pragma unroll
            for (int ks = 0; ks < 8; ++ks) {
                const uint32_t koff = ks * 32 + lc;
                uint32_t ah[4], bh[2][4];
                ldsm4(ah[0], ah[1], ah[2], ah[3], aBase + lr * ROWB + koff);
#pragma unroll
                for (int nj = 0; nj < 2; ++nj)
                    ldsm4(bh[nj][0], bh[nj][1], bh[nj][2], bh[nj][3],
                          bBase + (nj * 16 + lr) * ROWB + koff);
#pragma unroll
                for (int nj = 0; nj < 2; ++nj)
#pragma unroll
                    for (int t = 0; t < 2; ++t)
                        mma16816(acc[nj * 2 + t], ah, bh[nj][t], bh[nj][t + 2]);
            }
            __syncthreads();
            if (i + 2 < NCHUNK) load_chunk(i + 2, s);
            cp_commit();
        }

        // ---- bias + relu -> hidden into Hs[64][64] ----
        __syncthreads();   // GEMM smem dead; reuse as Hs
#pragma unroll
        for (int nt = 0; nt < 4; ++nt) {
            const int col = wn + (nt >> 1) * 16 + (nt & 1) * 8 + c0;
            const float2 bb = *(const float2*)(Gb1 + d * kGH + col);
#pragma unroll
            for (int h = 0; h < 2; ++h) {
                const int row = wm + r0 + h * 8;
                Hs[row * 64 + col]     = fmaxf(acc[nt][2 * h + 0] + bb.x, 0.f);
                Hs[row * 64 + col + 1] = fmaxf(acc[nt][2 * h + 1] + bb.y, 0.f);
            }
        }
        __syncthreads();

        // ---- per-sample tail: softmax + MMoE + tower ----
        for (int slot = w; slot < NS; slot += 8) {
            const int b = sid[slot];
            if (b < 0) continue;
            float g0 = Hs[slot * 64 + lane];
            float g1 = Hs[slot * 64 + lane + 32];

            float logit[kE];
#pragma unroll
            for (int e = 0; e < kE; ++e)
                logit[e] = g0 * Gw2[((size_t)d * kGH + lane) * kE + e]
                         + g1 * Gw2[((size_t)d * kGH + lane + 32) * kE + e];
#pragma unroll
            for (int e = 0; e < kE; ++e)
#pragma unroll
                for (int o = 16; o; o >>= 1)
                    logit[e] += __shfl_xor_sync(0xffffffffu, logit[e], o);

            float mx = -1e30f;
#pragma unroll
            for (int e = 0; e < kE; ++e) {
                logit[e] += Gb2[d * kE + e];
                mx = fmaxf(mx, logit[e]);
            }
            float se = 0.f, gw[kE];
#pragma unroll
            for (int e = 0; e < kE; ++e) { gw[e] = expf(logit[e] - mx); se += gw[e]; }
            float inv = 1.f / se;

            float mmoe = 0.f;
            if (lane < kEO) {
                float avg = 0.f;
#pragma unroll
                for (int e = 0; e < kE; ++e) {
                    float v = g_EO[((size_t)e * kB + b) * kEO + lane];
                    avg += v;
                    mmoe = fmaf(gw[e] * inv, v, mmoe);
                }
                out[kB + (size_t)b * kEO + lane] = avg * (1.f / 6.f);
                out[kB + (size_t)kB * kEO + (size_t)b * kEO + lane] = mmoe;
            }

            float mm[kEO];
#pragma unroll
            for (int o = 0; o < kEO; ++o)
                mm[o] = __shfl_sync(0xffffffffu, mmoe, o);

            float th0 = Tb1[d * 64 + lane];
            float th1 = Tb1[d * 64 + lane + 32];
#pragma unroll
            for (int o = 0; o < kEO; ++o) {
                th0 = fmaf(mm[o], Tw1[((size_t)d * kEO + o) * 64 + lane],      th0);
                th1 = fmaf(mm[o], Tw1[((size_t)d * kEO + o) * 64 + lane + 32], th1);
            }
            th0 = fmaxf(th0, 0.f);
            th1 = fmaxf(th1, 0.f);

            float s = th0 * Tw2[d * 64 + lane] + th1 * Tw2[d * 64 + lane + 32];
#pragma unroll
            for (int o = 16; o; o >>= 1)
                s += __shfl_xor_sync(0xffffffffu, s, o);

            if (lane == 0) {
                float z = s + Tb2[d];
                out[b] = 1.f / (1.f + expf(-z));
            }
        }
        __syncthreads();   // protect sid/Hs before next chunk
    }
}

// =====================================================================
// launch
// =====================================================================
extern "C" void kernel_launch(void* const* d_in, const int* in_sizes, int n_in,
                              void* d_out, int out_size)
{
    const float* x   = (const float*)d_in[0];
    const int*   dom = (const int*)  d_in[1];
    const float* Ew1 = (const float*)d_in[2];
    const float* Eb1 = (const float*)d_in[3];
    const float* Ew2 = (const float*)d_in[4];
    const float* Eb2 = (const float*)d_in[5];
    const float* Ew3 = (const float*)d_in[6];
    const float* Eb3 = (const float*)d_in[7];
    const float* Gw1 = (const float*)d_in[8];
    const float* Gb1 = (const float*)d_in[9];
    const float* Gw2 = (const float*)d_in[10];
    const float* Gb2 = (const float*)d_in[11];
    const float* Tw1 = (const float*)d_in[12];
    const float* Tb1 = (const float*)d_in[13];
    const float* Tw2 = (const float*)d_in[14];
    const float* Tb2 = (const float*)d_in[15];
    float* out = (float*)d_out;

    __half *Xh, *W1h, *W2h, *G1h, *H1h;
    cudaGetSymbolAddress((void**)&Xh,  g_Xh);
    cudaGetSymbolAddress((void**)&W1h, g_W1h);
    cudaGetSymbolAddress((void**)&W2h, g_W2h);
    cudaGetSymbolAddress((void**)&G1h, g_G1h);
    cudaGetSymbolAddress((void**)&H1h, g_H1h);

    constexpr int SMEM = 3 * 2 * 128 * 144;   // 110592 for expert GEMMs
    cudaFuncSetAttribute(mma_gemm<kEH1, kIN, true, false>,
                         cudaFuncAttributeMaxDynamicSharedMemorySize, SMEM);
    cudaFuncSetAttribute(mma_gemm<kEH2, kEH1, false, true>,
                         cudaFuncAttributeMaxDynamicSharedMemorySize, SMEM);
    constexpr int GSMEM = 2 * 2 * NS * 272;   // 69632 for gate kernel
    cudaFuncSetAttribute(gate_tower_bucketed,
                         cudaFuncAttributeMaxDynamicSharedMemorySize, GSMEM);

    // --- bucketing (single kernel) ---
    bucket_all<<<1, 1024>>>(dom);

    // --- prep: x -> fp16, transpose W1/W2/Gw1 to fp16 ---
    cvt_x_kernel<<<(kB * kIN / 8) / 256, 256>>>((const float4*)x, (uint4*)Xh);
    transpose_h_kernel<<<dim3(kIN / 32, kEH1 / 32, kE), dim3(32, 8)>>>(
        Ew1, W1h, kIN, kEH1);
    transpose_h_kernel<<<dim3(kEH1 / 32, kEH2 / 32, kE), dim3(32, 8)>>>(
        Ew2, W2h, kEH1, kEH2);
    transpose_h_kernel<<<dim3(kIN / 32, kGH / 32, kD), dim3(32, 8)>>>(
        Gw1, G1h, kIN, kGH);

    // --- expert L1 (HMMA fp16): H1 = relu(x @ Ew1 + b), fp16 out ---
    mma_gemm<kEH1, kIN, true, false><<<dim3(kEH1 / 128, kB / 128, kE), 256, SMEM>>>(
        Xh, W1h, Eb1, /*aStride=*/0, H1h, nullptr, nullptr);

    // --- expert L2+L3 fused: H2 = relu(H1 @ Ew2 + b); EO = H2 @ Ew3 + b3 ---
    mma_gemm<kEH2, kEH1, false, true><<<dim3(1, kB / 128, kE), 256, SMEM>>>(
        H1h, W2h, Eb2, /*aStride=*/(size_t)kB * kEH1, nullptr, Ew3, Eb3);

    // --- bucketed HMMA gate + MMoE + tower + outputs ---
    gate_tower_bucketed<<<dim3(GCH, kD), 256, GSMEM>>>(x, Gb1, Gw2, Gb2,
                                                       Tw1, Tb1, Tw2, Tb2, out);
}

// round 17
// speedup vs baseline: 4.3887x; 1.0971x over previous
#include <cuda_runtime.h>
#include <cuda_fp16.h>
#include <math.h>
#include <stdint.h>

// ---------------- problem constants ----------------
constexpr int kB   = 16384;
constexpr int kIN  = 1024;
constexpr int kE   = 6;
constexpr int kD   = 20;
constexpr int kEH1 = 256;
constexpr int kEH2 = 128;
constexpr int kEO  = 10;
constexpr int kGH  = 64;

// ---------------- scratch (device globals: no allocs allowed) ----------------
__device__ __half g_Xh[(size_t)kB * kIN];                  // fp16 x
__device__ __half g_W1h[(size_t)kE * kEH1 * kIN];          // [E][N=256][K=1024] fp16 (transposed)
__device__ __half g_W2h[(size_t)kE * kEH2 * kEH1];         // [E][N=128][K=256]  fp16
__device__ __half g_G1h[(size_t)kD * kGH * kIN];           // [D][N=64][K=1024]  fp16 (transposed)
__device__ float  g_EO[(size_t)kE * kB * kEO];             // expert outputs

// domain bucketing scratch
__device__ int g_cnt[kD];
__device__ int g_off[kD];
__device__ int g_order[kB];

// =====================================================================
// PTX helpers (sm_80-era ISA — harness targets plain sm_103, no tcgen05)
// =====================================================================
__device__ __forceinline__ uint32_t smem_u32(const void* p) {
    return (uint32_t)__cvta_generic_to_shared(p);
}
__device__ __forceinline__ void cp_async16(uint32_t dst, const void* src) {
    asm volatile("cp.async.cg.shared.global [%0], [%1], 16;" :: "r"(dst), "l"(src));
}
__device__ __forceinline__ void cp_commit() { asm volatile("cp.async.commit_group;" ::: "memory"); }
__device__ __forceinline__ void cp_wait2()  { asm volatile("cp.async.wait_group 2;" ::: "memory"); }
__device__ __forceinline__ void cp_wait1()  { asm volatile("cp.async.wait_group 1;" ::: "memory"); }
__device__ __forceinline__ void cp_wait0()  { asm volatile("cp.async.wait_group 0;" ::: "memory"); }

__device__ __forceinline__ void ldsm4(uint32_t& r0, uint32_t& r1, uint32_t& r2, uint32_t& r3,
                                      uint32_t addr) {
    asm volatile("ldmatrix.sync.aligned.m8n8.x4.shared.b16 {%0,%1,%2,%3}, [%4];"
                 : "=r"(r0), "=r"(r1), "=r"(r2), "=r"(r3) : "r"(addr));
}
__device__ __forceinline__ void mma16816(float* c, const uint32_t* a, uint32_t b0, uint32_t b1) {
    asm volatile("mma.sync.aligned.m16n8k16.row.col.f32.f16.f16.f32 "
                 "{%0,%1,%2,%3},{%4,%5,%6,%7},{%8,%9},{%0,%1,%2,%3};"
                 : "+f"(c[0]), "+f"(c[1]), "+f"(c[2]), "+f"(c[3])
                 : "r"(a[0]), "r"(a[1]), "r"(a[2]), "r"(a[3]), "r"(b0), "r"(b1));
}

// =====================================================================
// Prep: x fp32 -> fp16 (8 elems/thread, 16B stores)
// =====================================================================
__global__ __launch_bounds__(256)
void cvt_x_kernel(const float4* __restrict__ x, uint4* __restrict__ out)
{
    size_t i = (size_t)blockIdx.x * 256 + threadIdx.x;
    float4 a = x[2 * i], b = x[2 * i + 1];
    __half2 h0 = __float22half2_rn(make_float2(a.x, a.y));
    __half2 h1 = __float22half2_rn(make_float2(a.z, a.w));
    __half2 h2 = __float22half2_rn(make_float2(b.x, b.y));
    __half2 h3 = __float22half2_rn(make_float2(b.z, b.w));
    uint4 o;
    o.x = *(uint32_t*)&h0; o.y = *(uint32_t*)&h1;
    o.z = *(uint32_t*)&h2; o.w = *(uint32_t*)&h3;
    out[i] = o;
}

// =====================================================================
// Prep: W [Z][K][N] fp32 -> W^T fp16 [Z][N][K]
// =====================================================================
__global__ __launch_bounds__(256)
void transpose_h_kernel(const float* __restrict__ W, __half* __restrict__ hi,
                        int K, int N)
{
    __shared__ float t[32][33];
    const int e = blockIdx.z;
    const float* We = W + (size_t)e * K * N;
    const int k0 = blockIdx.x * 32, n0 = blockIdx.y * 32;
    const int tx = threadIdx.x, ty = threadIdx.y;
    for (int i = ty; i < 32; i += 8)
        t[i][tx] = We[(size_t)(k0 + i) * N + n0 + tx];
    __syncthreads();
    for (int i = ty; i < 32; i += 8) {
        size_t o = ((size_t)e * N + n0 + i) * K + k0 + tx;
        hi[o] = __float2half(t[tx][i]);   // = W[k0+tx][n0+i]
    }
}

// =====================================================================
// FULLY FUSED expert kernel. One CTA = 128 samples x one expert.
//  Phase 1: H1 = relu(x @ Ew1^T + b1)  [128x256] — HMMA, K=1024,
//           3-stage cp.async, 16 warps (4m x 4n), warp 32x64.
//           Result kept in smem as fp16 (row stride 528B, conflict-free).
//  Phase 2: H2 = relu(H1 @ Ew2^T + b2) [128x128] — HMMA from smem,
//           16 warps (4m x 4n), warp 32x32, K=256.
//  Phase 3: EO = H2 @ Ew3 + b3         [128x10]  — warp reduction.
// =====================================================================
__global__ __launch_bounds__(512)
void expert_fused(const __half* __restrict__ Xh,
                  const __half* __restrict__ W1_all,
                  const __half* __restrict__ W2_all,
                  const float* __restrict__ Eb1, const float* __restrict__ Eb2,
                  const float* __restrict__ Ew3, const float* __restrict__ Eb3)
{
    constexpr int BK = 64;
    constexpr int NCHUNK = kIN / BK;          // 16
    constexpr int ROWB = 144;                 // 128B data + 16B pad
    constexpr int A_SZ = 128 * ROWB;          // 18432
    constexpr int W_SZ = 256 * ROWB;          // 36864
    constexpr int STAGE = A_SZ + W_SZ;        // 55296 ; 3 stages = 165888
    constexpr int ROWH = 528;                 // 256 halves + 16B pad (132w%32=4 -> ok)
    constexpr int H1S_OFF = 0;                // H1 fp16 [128][ROWH]   -> 67584
    constexpr int W2_OFF  = 128 * ROWH;       // W2 fp16 [128][ROWH]   -> 67584
    constexpr int H2_OFF  = 2 * 128 * ROWH;   // H2 fp32 [128][132]    -> 67584
    constexpr int RS = 132;
    // dynamic smem = max(165888, 202752) = 202752

    extern __shared__ char dsm[];
    const uint32_t sb = smem_u32(dsm);
    __shared__ float Ws[kEH2 * kEO];
    __shared__ float bs[kEO];

    const int tid  = threadIdx.x;
    const int w    = tid >> 5;
    const int lane = tid & 31;
    const int e     = blockIdx.y;
    const int mBase = blockIdx.x * 128;
    const int wm  = (w & 3) * 32;             // phase-1/2 row group
    const int wn  = (w >> 2) * 64;            // phase-1 col group (4x64=256)
    const int wn2 = (w >> 2) * 32;            // phase-2 col group (4x32=128)

    const __half* W1 = W1_all + (size_t)e * kEH1 * kIN;
    const __half* W2 = W2_all + (size_t)e * kEH2 * kEH1;

    auto load_chunk = [&](int c, int s) {
        const uint32_t st = sb + s * STAGE;
        // A: 128 rows x 8 granules = 1024 ; W1: 256 rows x 8 = 2048
#pragma unroll
        for (int g = tid; g < 3072; g += 512) {
            if (g < 1024) {
                const int row = g >> 3, gr = g & 7;
                cp_async16(st + row * ROWB + gr * 16,
                           Xh + (size_t)(mBase + row) * kIN + c * BK + gr * 8);
            } else {
                const int idx = g - 1024;
                const int row = idx >> 3, gr = idx & 7;
                cp_async16(st + A_SZ + row * ROWB + gr * 16,
                           W1 + (size_t)row * kIN + c * BK + gr * 8);
            }
        }
    };

    float acc[2][8][4];
#pragma unroll
    for (int i = 0; i < 2; ++i)
#pragma unroll
        for (int j = 0; j < 8; ++j)
#pragma unroll
            for (int q = 0; q < 4; ++q) acc[i][j][q] = 0.f;

    load_chunk(0, 0); cp_commit();
    load_chunk(1, 1); cp_commit();
    load_chunk(2, 2); cp_commit();

    const int lr = lane & 15;
    const int lc = (lane >> 4) * 16;
    const int r0 = lane >> 2;
    const int c0 = (lane & 3) * 2;

    // ---------------- phase 1 mainloop ----------------
    int s = 0;
    for (int i = 0; i < NCHUNK; ++i) {
        cp_wait2();
        __syncthreads();
        const uint32_t st    = sb + s * STAGE;
        const uint32_t aBase = st + wm * ROWB;
        const uint32_t bBase = st + A_SZ + wn * ROWB;

#pragma unroll
        for (int ks = 0; ks < 4; ++ks) {
            const uint32_t koff = ks * 32 + lc;
            uint32_t ah[2][4], bh[4][4];
#pragma unroll
            for (int mi = 0; mi < 2; ++mi)
                ldsm4(ah[mi][0], ah[mi][1], ah[mi][2], ah[mi][3],
                      aBase + (mi * 16 + lr) * ROWB + koff);
#pragma unroll
            for (int nj = 0; nj < 4; ++nj)
                ldsm4(bh[nj][0], bh[nj][1], bh[nj][2], bh[nj][3],
                      bBase + (nj * 16 + lr) * ROWB + koff);
#pragma unroll
            for (int mi = 0; mi < 2; ++mi)
#pragma unroll
                for (int nj = 0; nj < 4; ++nj)
#pragma unroll
                    for (int t = 0; t < 2; ++t)
                        mma16816(acc[mi][nj * 2 + t], ah[mi], bh[nj][t], bh[nj][t + 2]);
        }
        __syncthreads();
        if (i + 3 < NCHUNK) load_chunk(i + 3, s);
        cp_commit();
        s = (s == 2) ? 0 : s + 1;
    }
    // all compute done; pipeline smem is dead (trailing sync inside loop)

    // ---------------- phase 1 -> 2 transition ----------------
    // issue W2 loads first (overlap with H1 stores), then Ew3/Eb3
#pragma unroll
    for (int g = tid; g < 4096; g += 512) {
        const int row = g >> 5, gr = g & 31;
        cp_async16(sb + W2_OFF + row * ROWH + gr * 16,
                   W2 + (size_t)row * kEH1 + gr * 8);
    }
    cp_commit();
    for (int i = tid; i < kEH2 * kEO; i += 512)
        Ws[i] = Ew3[(size_t)e * kEH2 * kEO + i];
    if (tid < kEO) bs[tid] = Eb3[e * kEO + tid];

    // store H1 (bias+relu, fp16) into smem
    {
        const float* be1 = Eb1 + e * kEH1;
#pragma unroll
        for (int mi = 0; mi < 2; ++mi)
#pragma unroll
            for (int nt = 0; nt < 8; ++nt) {
                const int col = wn + (nt >> 1) * 16 + (nt & 1) * 8 + c0;
                const float2 bb = *(const float2*)(be1 + col);
#pragma unroll
                for (int h = 0; h < 2; ++h) {
                    const int row = wm + mi * 16 + r0 + h * 8;
                    float v0 = fmaxf(acc[mi][nt][2 * h + 0] + bb.x, 0.f);
                    float v1 = fmaxf(acc[mi][nt][2 * h + 1] + bb.y, 0.f);
                    *(__half2*)(dsm + H1S_OFF + row * ROWH + col * 2) =
                        __float22half2_rn(make_float2(v0, v1));
                }
            }
    }
    cp_wait0();
    __syncthreads();

    // ---------------- phase 2: H2 = relu(H1 @ W2^T + b2) ----------------
    float acc2[2][4][4];
#pragma unroll
    for (int i = 0; i < 2; ++i)
#pragma unroll
        for (int j = 0; j < 4; ++j)
#pragma unroll
            for (int q = 0; q < 4; ++q) acc2[i][j][q] = 0.f;

#pragma unroll
    for (int ks = 0; ks < 16; ++ks) {
        const uint32_t koff = ks * 32 + lc;
        uint32_t ah[2][4], bh[2][4];
#pragma unroll
        for (int mi = 0; mi < 2; ++mi)
            ldsm4(ah[mi][0], ah[mi][1], ah[mi][2], ah[mi][3],
                  sb + H1S_OFF + (wm + mi * 16 + lr) * ROWH + koff);
#pragma unroll
        for (int nj = 0; nj < 2; ++nj)
            ldsm4(bh[nj][0], bh[nj][1], bh[nj][2], bh[nj][3],
                  sb + W2_OFF + (wn2 + nj * 16 + lr) * ROWH + koff);
#pragma unroll
        for (int mi = 0; mi < 2; ++mi)
#pragma unroll
            for (int nj = 0; nj < 2; ++nj)
#pragma unroll
                for (int t = 0; t < 2; ++t)
                    mma16816(acc2[mi][nj * 2 + t], ah[mi], bh[nj][t], bh[nj][t + 2]);
    }

    // H2 (bias+relu, fp32) into smem (distinct region — no sync needed first)
    {
        float* H2s = (float*)(dsm + H2_OFF);
        const float* be2 = Eb2 + e * kEH2;
#pragma unroll
        for (int mi = 0; mi < 2; ++mi)
#pragma unroll
            for (int nt = 0; nt < 4; ++nt) {
                const int col = wn2 + (nt >> 1) * 16 + (nt & 1) * 8 + c0;
                const float2 bb = *(const float2*)(be2 + col);
#pragma unroll
                for (int h = 0; h < 2; ++h) {
                    const int row = wm + mi * 16 + r0 + h * 8;
                    H2s[row * RS + col]     = fmaxf(acc2[mi][nt][2 * h + 0] + bb.x, 0.f);
                    H2s[row * RS + col + 1] = fmaxf(acc2[mi][nt][2 * h + 1] + bb.y, 0.f);
                }
            }
    }
    __syncthreads();

    // ---------------- phase 3: EO = H2 @ Ew3 + b3 ----------------
    {
        const float* H2s = (const float*)(dsm + H2_OFF);
        for (int r = w * 8; r < w * 8 + 8; ++r) {
            float4 hv = *(const float4*)&H2s[r * RS + lane * 4];
            float o[kEO];
#pragma unroll
            for (int j = 0; j < kEO; ++j) {
                o[j] = hv.x * Ws[(lane * 4 + 0) * kEO + j]
                     + hv.y * Ws[(lane * 4 + 1) * kEO + j]
                     + hv.z * Ws[(lane * 4 + 2) * kEO + j]
                     + hv.w * Ws[(lane * 4 + 3) * kEO + j];
            }
#pragma unroll
            for (int j = 0; j < kEO; ++j)
#pragma unroll
                for (int off = 16; off; off >>= 1)
                    o[j] += __shfl_xor_sync(0xffffffffu, o[j], off);
#pragma unroll
            for (int j = 0; j < kEO; ++j)
                if (lane == j)
                    g_EO[((size_t)e * kB + mBase + r) * kEO + j] = o[j] + bs[j];
        }
    }
}

// =====================================================================
// Domain bucketing: single CTA, smem histogram + scan + scatter.
// =====================================================================
__global__ __launch_bounds__(1024)
void bucket_all(const int* __restrict__ dom)
{
    __shared__ int cnt[kD], cur[kD];
    const int t = threadIdx.x;
    if (t < kD) cnt[t] = 0;
    __syncthreads();
    for (int i = t; i < kB; i += 1024)
        atomicAdd(&cnt[dom[i]], 1);
    __syncthreads();
    if (t == 0) {
        int a = 0;
        for (int d = 0; d < kD; ++d) {
            g_off[d] = a; cur[d] = a; g_cnt[d] = cnt[d];
            a += cnt[d];
        }
    }
    __syncthreads();
    for (int i = t; i < kB; i += 1024) {
        int p = atomicAdd(&cur[dom[i]], 1);
        g_order[p] = i;
    }
}

// =====================================================================
// Bucketed gate (HMMA) + MMoE + tower. Each block-chunk = 64 samples of
// ONE domain. Hidden: gathered-x fp16 @ Gw1^T fp16 via mma.sync.
// =====================================================================
constexpr int NS  = 64;   // samples per block-chunk
constexpr int GCH = 16;   // grid.x stride over chunks

__global__ __launch_bounds__(256)
void gate_tower_bucketed(const float* __restrict__ x,
                         const float* __restrict__ Gb1,
                         const float* __restrict__ Gw2, const float* __restrict__ Gb2,
                         const float* __restrict__ Tw1, const float* __restrict__ Tb1,
                         const float* __restrict__ Tw2, const float* __restrict__ Tb2,
                         float* __restrict__ out)
{
    constexpr int BK   = 128;
    constexpr int ROWB = 272;               // 256B data + 16B pad
    constexpr int T_SZ = NS * ROWB;         // 17408
    constexpr int STAGE = 2 * T_SZ;         // 34816
    constexpr int NCHUNK = kIN / BK;        // 8

    extern __shared__ char dsm[];           // 2 stages = 69632
    const uint32_t sb = smem_u32(dsm);
    float* Hs = (float*)dsm;                // hidden [64][64] fp32, reused after GEMM

    __shared__ int sid[NS];

    const int d    = blockIdx.y;
    const int cnt  = g_cnt[d];
    const int off  = g_off[d];
    const int tid  = threadIdx.x;
    const int w    = tid >> 5;
    const int lane = tid & 31;

    const __half* Wd = g_G1h + (size_t)d * kGH * kIN;

    const int wm = (w & 3) * 16;
    const int wn = (w >> 2) * 32;
    const int lr = lane & 15;
    const int lc = (lane >> 4) * 16;
    const int r0 = lane >> 2;
    const int c0 = (lane & 3) * 2;

    for (int chunk = blockIdx.x; chunk * NS < cnt; chunk += GCH) {
        const int base = off + chunk * NS;
        const int ns   = min(NS, cnt - chunk * NS);
        if (tid < NS) sid[tid] = (tid < ns) ? g_order[base + tid] : -1;
        __syncthreads();

        auto load_chunk = [&](int c, int s) {
            const uint32_t st = sb + s * STAGE;
#pragma unroll
            for (int g = tid; g < 2048; g += 256) {
                const int seg = g >> 10;
                const int idx = g & 1023;
                const int row = idx >> 4, gr = idx & 15;
                const __half* src;
                if (seg == 0) {
                    int sr = sid[row];
                    src = g_Xh + (size_t)(sr < 0 ? 0 : sr) * kIN + c * BK + gr * 8;
                } else {
                    src = Wd + (size_t)row * kIN + c * BK + gr * 8;
                }
                cp_async16(st + seg * T_SZ + row * ROWB + gr * 16, src);
            }
        };

        float acc[4][4];
#pragma unroll
        for (int j = 0; j < 4; ++j)
#pragma unroll
            for (int q = 0; q < 4; ++q) acc[j][q] = 0.f;

        load_chunk(0, 0); cp_commit();
        load_chunk(1, 1); cp_commit();

        for (int i = 0; i < NCHUNK; ++i) {
            const int s = i & 1;
            cp_wait1();
            __syncthreads();
            const uint32_t st    = sb + s * STAGE;
            const uint32_t aBase = st + wm * ROWB;
            const uint32_t bBase = st + T_SZ + wn * ROWB;

#pragma unroll
            for (int ks = 0; ks < 8; ++ks) {
                const uint32_t koff = ks * 32 + lc;
                uint32_t ah[4], bh[2][4];
                ldsm4(ah[0], ah[1], ah[2], ah[3], aBase + lr * ROWB + koff);
#pragma unroll
                for (int nj = 0; nj < 2; ++nj)
                    ldsm4(bh[nj][0], bh[nj][1], bh[nj][2], bh[nj][3],
                          bBase + (nj * 16 + lr) * ROWB + koff);
#pragma unroll
                for (int nj = 0; nj < 2; ++nj)
#pragma unroll
                    for (int t = 0; t < 2; ++t)
                        mma16816(acc[nj * 2 + t], ah, bh[nj][t], bh[nj][t + 2]);
            }
            __syncthreads();
            if (i + 2 < NCHUNK) load_chunk(i + 2, s);
            cp_commit();
        }

        __syncthreads();
#pragma unroll
        for (int nt = 0; nt < 4; ++nt) {
            const int col = wn + (nt >> 1) * 16 + (nt & 1) * 8 + c0;
            const float2 bb = *(const float2*)(Gb1 + d * kGH + col);
#pragma unroll
            for (int h = 0; h < 2; ++h) {
                const int row = wm + r0 + h * 8;
                Hs[row * 64 + col]     = fmaxf(acc[nt][2 * h + 0] + bb.x, 0.f);
                Hs[row * 64 + col + 1] = fmaxf(acc[nt][2 * h + 1] + bb.y, 0.f);
            }
        }
        __syncthreads();

        for (int slot = w; slot < NS; slot += 8) {
            const int b = sid[slot];
            if (b < 0) continue;
            float g0 = Hs[slot * 64 + lane];
            float g1 = Hs[slot * 64 + lane + 32];

            float logit[kE];
#pragma unroll
            for (int e = 0; e < kE; ++e)
                logit[e] = g0 * Gw2[((size_t)d * kGH + lane) * kE + e]
                         + g1 * Gw2[((size_t)d * kGH + lane + 32) * kE + e];
#pragma unroll
            for (int e = 0; e < kE; ++e)
#pragma unroll
                for (int o = 16; o; o >>= 1)
                    logit[e] += __shfl_xor_sync(0xffffffffu, logit[e], o);

            float mx = -1e30f;
#pragma unroll
            for (int e = 0; e < kE; ++e) {
                logit[e] += Gb2[d * kE + e];
                mx = fmaxf(mx, logit[e]);
            }
            float se = 0.f, gw[kE];
#pragma unroll
            for (int e = 0; e < kE; ++e) { gw[e] = expf(logit[e] - mx); se += gw[e]; }
            float inv = 1.f / se;

            float mmoe = 0.f;
            if (lane < kEO) {
                float avg = 0.f;
#pragma unroll
                for (int e = 0; e < kE; ++e) {
                    float v = g_EO[((size_t)e * kB + b) * kEO + lane];
                    avg += v;
                    mmoe = fmaf(gw[e] * inv, v, mmoe);
                }
                out[kB + (size_t)b * kEO + lane] = avg * (1.f / 6.f);
                out[kB + (size_t)kB * kEO + (size_t)b * kEO + lane] = mmoe;
            }

            float mm[kEO];
#pragma unroll
            for (int o = 0; o < kEO; ++o)
                mm[o] = __shfl_sync(0xffffffffu, mmoe, o);

            float th0 = Tb1[d * 64 + lane];
            float th1 = Tb1[d * 64 + lane + 32];
#pragma unroll
            for (int o = 0; o < kEO; ++o) {
                th0 = fmaf(mm[o], Tw1[((size_t)d * kEO + o) * 64 + lane],      th0);
                th1 = fmaf(mm[o], Tw1[((size_t)d * kEO + o) * 64 + lane + 32], th1);
            }
            th0 = fmaxf(th0, 0.f);
            th1 = fmaxf(th1, 0.f);

            float s = th0 * Tw2[d * 64 + lane] + th1 * Tw2[d * 64 + lane + 32];
#pragma unroll
            for (int o = 16; o; o >>= 1)
                s += __shfl_xor_sync(0xffffffffu, s, o);

            if (lane == 0) {
                float z = s + Tb2[d];
                out[b] = 1.f / (1.f + expf(-z));
            }
        }
        __syncthreads();
    }
}

// =====================================================================
// launch
// =====================================================================
extern "C" void kernel_launch(void* const* d_in, const int* in_sizes, int n_in,
                              void* d_out, int out_size)
{
    const float* x   = (const float*)d_in[0];
    const int*   dom = (const int*)  d_in[1];
    const float* Ew1 = (const float*)d_in[2];
    const float* Eb1 = (const float*)d_in[3];
    const float* Ew2 = (const float*)d_in[4];
    const float* Eb2 = (const float*)d_in[5];
    const float* Ew3 = (const float*)d_in[6];
    const float* Eb3 = (const float*)d_in[7];
    const float* Gw1 = (const float*)d_in[8];
    const float* Gb1 = (const float*)d_in[9];
    const float* Gw2 = (const float*)d_in[10];
    const float* Gb2 = (const float*)d_in[11];
    const float* Tw1 = (const float*)d_in[12];
    const float* Tb1 = (const float*)d_in[13];
    const float* Tw2 = (const float*)d_in[14];
    const float* Tb2 = (const float*)d_in[15];
    float* out = (float*)d_out;

    __half *Xh, *W1h, *W2h, *G1h;
    cudaGetSymbolAddress((void**)&Xh,  g_Xh);
    cudaGetSymbolAddress((void**)&W1h, g_W1h);
    cudaGetSymbolAddress((void**)&W2h, g_W2h);
    cudaGetSymbolAddress((void**)&G1h, g_G1h);

    constexpr int FSMEM = 2 * 128 * 528 + 128 * 132 * 4;   // 202752 (phase2 layout > 3-stage 165888)
    cudaFuncSetAttribute(expert_fused,
                         cudaFuncAttributeMaxDynamicSharedMemorySize, FSMEM);
    constexpr int GSMEM = 2 * 2 * NS * 272;   // 69632
    cudaFuncSetAttribute(gate_tower_bucketed,
                         cudaFuncAttributeMaxDynamicSharedMemorySize, GSMEM);

    // --- bucketing (single kernel) ---
    bucket_all<<<1, 1024>>>(dom);

    // --- prep: x -> fp16, transpose W1/W2/Gw1 to fp16 ---
    cvt_x_kernel<<<(kB * kIN / 8) / 256, 256>>>((const float4*)x, (uint4*)Xh);
    transpose_h_kernel<<<dim3(kIN / 32, kEH1 / 32, kE), dim3(32, 8)>>>(
        Ew1, W1h, kIN, kEH1);
    transpose_h_kernel<<<dim3(kEH1 / 32, kEH2 / 32, kE), dim3(32, 8)>>>(
        Ew2, W2h, kEH1, kEH2);
    transpose_h_kernel<<<dim3(kIN / 32, kGH / 32, kD), dim3(32, 8)>>>(
        Gw1, G1h, kIN, kGH);

    // --- fully fused expert stack: L1 + L2 + L3 in one kernel ---
    expert_fused<<<dim3(kB / 128, kE), 512, FSMEM>>>(
        Xh, W1h, W2h, Eb1, Eb2, Ew3, Eb3);

    // --- bucketed HMMA gate + MMoE + tower + outputs ---
    gate_tower_bucketed<<<dim3(GCH, kD), 256, GSMEM>>>(x, Gb1, Gw2, Gb2,
                                                       Tw1, Tb1, Tw2, Tb2, out);
}